// round 3
// baseline (speedup 1.0000x reference)
#include <cuda_runtime.h>

// ---------------------------------------------------------------------------
// HAttention1D: b=4 h=8 n=8192 d=64, block=16, 9 levels (0..8).
// Levels grouped in threes: K1 = levels 0-2 (+pool to lvl3),
// K2 = levels 3-5 (+pool to lvl6), K3 = levels 6-8, K4 = combine/divide.
// ---------------------------------------------------------------------------

#define BHN 32
#define N0  8192
#define DD  64
#define SD  68   // padded smem row stride in floats (272B -> <=2-way conflicts)

// ---- scratch (device globals; no allocations allowed) ----
__device__ __align__(16) float g_Y012[(size_t)BHN * N0 * DD];        // 64 MB
__device__ __align__(16) float g_A012[BHN * N0];
__device__ __align__(16) float g_q3[BHN * (N0 / 8) * DD];            // 8 MB each
__device__ __align__(16) float g_k3[BHN * (N0 / 8) * DD];
__device__ __align__(16) float g_v3[BHN * (N0 / 8) * DD];
__device__ __align__(16) float g_Y345[BHN * (N0 / 8) * DD];
__device__ __align__(16) float g_A345[BHN * (N0 / 8)];
__device__ __align__(16) float g_q6[BHN * (N0 / 64) * DD];
__device__ __align__(16) float g_k6[BHN * (N0 / 64) * DD];
__device__ __align__(16) float g_v6[BHN * (N0 / 64) * DD];
__device__ __align__(16) float g_Y678[BHN * (N0 / 64) * DD];
__device__ __align__(16) float g_A678[BHN * (N0 / 64)];

// ---- float4 helpers ----
__device__ __forceinline__ float4 f4_add(float4 a, float4 b) {
    return make_float4(a.x + b.x, a.y + b.y, a.z + b.z, a.w + b.w);
}
__device__ __forceinline__ float4 f4_avg(float4 a, float4 b) {
    return make_float4((a.x + b.x) * 0.5f, (a.y + b.y) * 0.5f,
                       (a.z + b.z) * 0.5f, (a.w + b.w) * 0.5f);
}

// ---------------------------------------------------------------------------
// One warp computes a full 16x16 block attention (S = qb@kb^T, rowmax, exp,
// y = A@vb, a = rowsum(A)) and writes y (16 x 64, stride SD) + a to smem.
// Lane mapping: i = lane&15 (query row), jh = lane>>4 (key-column half).
// ---------------------------------------------------------------------------
__device__ __forceinline__ void attn16_smem(const float* __restrict__ qB,
                                            const float* __restrict__ kB,
                                            const float* __restrict__ vB,
                                            float* __restrict__ yOut,
                                            float* __restrict__ aOut,
                                            int lane)
{
    const int i = lane & 15;
    const int jh = lane >> 4;
    const float* qr = qB + i * SD;
    const float* kr = kB + jh * 8 * SD;

    float acc[8];
#pragma unroll
    for (int jj = 0; jj < 8; jj++) acc[jj] = 0.f;

#pragma unroll
    for (int c4 = 0; c4 < 16; c4++) {
        float4 qv = *(const float4*)(qr + c4 * 4);
#pragma unroll
        for (int jj = 0; jj < 8; jj++) {
            float4 kv = *(const float4*)(kr + jj * SD + c4 * 4);
            acc[jj] += qv.x * kv.x + qv.y * kv.y + qv.z * kv.z + qv.w * kv.w;
        }
    }

    float m = acc[0];
#pragma unroll
    for (int jj = 1; jj < 8; jj++) m = fmaxf(m, acc[jj]);
    m = fmaxf(m, __shfl_xor_sync(0xffffffffu, m, 16));

    float A[8];
    float rs = 0.f;
#pragma unroll
    for (int jj = 0; jj < 8; jj++) { A[jj] = __expf(acc[jj] - m); rs += A[jj]; }
    rs += __shfl_xor_sync(0xffffffffu, rs, 16);
    if (jh == 0) aOut[i] = rs;

    const float* vr = vB + jh * 8 * SD;
#pragma unroll
    for (int c4 = 0; c4 < 16; c4++) {
        float yx = 0.f, yy = 0.f, yz = 0.f, yw = 0.f;
#pragma unroll
        for (int jj = 0; jj < 8; jj++) {
            float4 vv = *(const float4*)(vr + jj * SD + c4 * 4);
            yx += A[jj] * vv.x; yy += A[jj] * vv.y;
            yz += A[jj] * vv.z; yw += A[jj] * vv.w;
        }
        yx += __shfl_xor_sync(0xffffffffu, yx, 16);
        yy += __shfl_xor_sync(0xffffffffu, yy, 16);
        yz += __shfl_xor_sync(0xffffffffu, yz, 16);
        yw += __shfl_xor_sync(0xffffffffu, yw, 16);
        if (jh == 0) *(float4*)(yOut + i * SD + c4 * 4) = make_float4(yx, yy, yz, yw);
    }
}

// ---------------------------------------------------------------------------
// Tri-level kernel: chunk of 128 tokens at this kernel's finest sub-level.
// Computes 3 consecutive levels, writes combined Y (=y0+y1+y2 at finest
// resolution) + combined A, and (optionally) pools to the next tri-level.
// FLIP0: does sub-level 0 use the sibling block (true for coarse levels)?
// ---------------------------------------------------------------------------
template <bool FLIP0, bool POOL>
__global__ __launch_bounds__(256, 1)
void hatt_tri(const float* __restrict__ Q, const float* __restrict__ K,
              const float* __restrict__ V, int ntok, float qscale,
              float* __restrict__ Yout, float* __restrict__ Aout,
              float* __restrict__ Qp, float* __restrict__ Kp,
              float* __restrict__ Vp)
{
    extern __shared__ float sm[];
    float* s_q0 = sm;                    // 128*SD  (reused as Y stage later)
    float* s_k0 = s_q0 + 128 * SD;       // 128*SD
    float* s_v0 = s_k0 + 128 * SD;       // 128*SD
    float* s_q1 = s_v0 + 128 * SD;       // 64*SD
    float* s_k1 = s_q1 + 64 * SD;
    float* s_v1 = s_k1 + 64 * SD;
    float* s_q2 = s_v1 + 64 * SD;        // 32*SD
    float* s_k2 = s_q2 + 32 * SD;
    float* s_v2 = s_k2 + 32 * SD;
    float* s_y1 = s_v2 + 32 * SD;        // 64*SD
    float* s_y2 = s_y1 + 64 * SD;        // 32*SD
    float* s_a1 = s_y2 + 32 * SD;        // 64
    float* s_a2 = s_a1 + 64;             // 32
    float* s_aS = s_a2 + 32;             // 128

    const int tid = threadIdx.x;
    const int bh = blockIdx.y;
    const int c = blockIdx.x;
    const size_t base = ((size_t)bh * (size_t)ntok + (size_t)c * 128) * DD;

    // ---- Phase 1: load chunk (q scaled) ----
    const float4* qg = (const float4*)(Q + base);
    const float4* kg = (const float4*)(K + base);
    const float4* vg = (const float4*)(V + base);
    for (int idx = tid; idx < 2048; idx += 256) {
        int row = idx >> 4, c4 = (idx & 15) << 2;
        float4 a = qg[idx];
        a.x *= qscale; a.y *= qscale; a.z *= qscale; a.w *= qscale;
        *(float4*)(s_q0 + row * SD + c4) = a;
        *(float4*)(s_k0 + row * SD + c4) = kg[idx];
        *(float4*)(s_v0 + row * SD + c4) = vg[idx];
    }
    __syncthreads();

    // ---- Phase 2a: pool to sub-level 1 (64 tokens) ----
    for (int idx = tid; idx < 64 * 16; idx += 256) {
        int t = idx >> 4, c4 = (idx & 15) << 2;
        int r0 = (2 * t) * SD + c4, r1 = (2 * t + 1) * SD + c4, rd = t * SD + c4;
        *(float4*)(s_q1 + rd) = f4_avg(*(const float4*)(s_q0 + r0), *(const float4*)(s_q0 + r1));
        *(float4*)(s_k1 + rd) = f4_avg(*(const float4*)(s_k0 + r0), *(const float4*)(s_k0 + r1));
        *(float4*)(s_v1 + rd) = f4_add(*(const float4*)(s_v0 + r0), *(const float4*)(s_v0 + r1));
    }
    __syncthreads();

    // ---- Phase 2b: pool to sub-level 2 (32 tokens) ----
    for (int idx = tid; idx < 32 * 16; idx += 256) {
        int t = idx >> 4, c4 = (idx & 15) << 2;
        int r0 = (2 * t) * SD + c4, r1 = (2 * t + 1) * SD + c4, rd = t * SD + c4;
        *(float4*)(s_q2 + rd) = f4_avg(*(const float4*)(s_q1 + r0), *(const float4*)(s_q1 + r1));
        *(float4*)(s_k2 + rd) = f4_avg(*(const float4*)(s_k1 + r0), *(const float4*)(s_k1 + r1));
        *(float4*)(s_v2 + rd) = f4_add(*(const float4*)(s_v1 + r0), *(const float4*)(s_v1 + r1));
    }
    __syncthreads();

    const int w = tid >> 5;
    const int lane = tid & 31;

    // ---- Phase 3 (parallel warps):
    //  warps 0-1: sub-level 2 attention (2 blocks, sibling flip)
    //  warps 2-5: sub-level 1 attention (4 blocks, sibling flip)
    //  warps 6-7: pool to next tri-level (global write), if POOL
    if (w < 2) {
        int qb = w, sb = w ^ 1;
        attn16_smem(s_q2 + qb * 16 * SD, s_k2 + sb * 16 * SD, s_v2 + sb * 16 * SD,
                    s_y2 + qb * 16 * SD, s_a2 + qb * 16, lane);
    } else if (w < 6) {
        int qb = w - 2, sb = qb ^ 1;
        attn16_smem(s_q1 + qb * 16 * SD, s_k1 + sb * 16 * SD, s_v1 + sb * 16 * SD,
                    s_y1 + qb * 16 * SD, s_a1 + qb * 16, lane);
    } else if (POOL) {
        int t2 = tid - 192;  // 0..63
        for (int idx = t2; idx < 16 * 16; idx += 64) {
            int t = idx >> 4, c4 = (idx & 15) << 2;
            int r0 = (2 * t) * SD + c4, r1 = (2 * t + 1) * SD + c4;
            size_t gi = ((size_t)bh * (size_t)(ntok >> 3) + (size_t)(c * 16 + t)) * DD + c4;
            *(float4*)(Qp + gi) = f4_avg(*(const float4*)(s_q2 + r0), *(const float4*)(s_q2 + r1));
            *(float4*)(Kp + gi) = f4_avg(*(const float4*)(s_k2 + r0), *(const float4*)(s_k2 + r1));
            *(float4*)(Vp + gi) = f4_add(*(const float4*)(s_v2 + r0), *(const float4*)(s_v2 + r1));
        }
    }
    __syncthreads();

    // ---- Phase 4: sub-level 0 attention (8 blocks, warp w -> block w)
    //      + in-register combine with y1/y2, stage result into s_q0 region.
    {
        const int i = lane & 15;
        const int dg = lane >> 4;  // also the key-column half for S
        const int sb = FLIP0 ? (w ^ 1) : w;
        const float* qB = s_q0 + w * 16 * SD;
        const float* kB = s_k0 + sb * 16 * SD;
        const float* vB = s_v0 + sb * 16 * SD;

        // S (j-split)
        const float* qr = qB + i * SD;
        const float* kr = kB + dg * 8 * SD;
        float acc[8];
#pragma unroll
        for (int jj = 0; jj < 8; jj++) acc[jj] = 0.f;
#pragma unroll
        for (int c4 = 0; c4 < 16; c4++) {
            float4 qv = *(const float4*)(qr + c4 * 4);
#pragma unroll
            for (int jj = 0; jj < 8; jj++) {
                float4 kv = *(const float4*)(kr + jj * SD + c4 * 4);
                acc[jj] += qv.x * kv.x + qv.y * kv.y + qv.z * kv.z + qv.w * kv.w;
            }
        }
        float m = acc[0];
#pragma unroll
        for (int jj = 1; jj < 8; jj++) m = fmaxf(m, acc[jj]);
        m = fmaxf(m, __shfl_xor_sync(0xffffffffu, m, 16));
        float A[8];
        float rs = 0.f;
#pragma unroll
        for (int jj = 0; jj < 8; jj++) { A[jj] = __expf(acc[jj] - m); rs += A[jj]; }
        rs += __shfl_xor_sync(0xffffffffu, rs, 16);  // full row sum on both lanes

        // exchange halves so every lane holds the full 16-wide A row
        float Af0[8], Af1[8];  // columns 0..7 / 8..15
#pragma unroll
        for (int jj = 0; jj < 8; jj++) {
            float o = __shfl_xor_sync(0xffffffffu, A[jj], 16);
            Af0[jj] = dg ? o : A[jj];
            Af1[jj] = dg ? A[jj] : o;
        }

        __syncthreads();  // everyone finished reading s_q0/s_k0 -> safe to reuse s_q0

        // y (d-split): lane covers dims [dg*32, dg*32+32)
        float4 yacc[8];
#pragma unroll
        for (int cc = 0; cc < 8; cc++) yacc[cc] = make_float4(0.f, 0.f, 0.f, 0.f);
#pragma unroll
        for (int jj = 0; jj < 8; jj++) {
            const float* vr0 = vB + jj * SD + (dg << 5);
            const float* vr1 = vB + (8 + jj) * SD + (dg << 5);
#pragma unroll
            for (int cc = 0; cc < 8; cc++) {
                float4 v0 = *(const float4*)(vr0 + cc * 4);
                float4 v1 = *(const float4*)(vr1 + cc * 4);
                yacc[cc].x += Af0[jj] * v0.x + Af1[jj] * v1.x;
                yacc[cc].y += Af0[jj] * v0.y + Af1[jj] * v1.y;
                yacc[cc].z += Af0[jj] * v0.z + Af1[jj] * v1.z;
                yacc[cc].w += Af0[jj] * v0.w + Af1[jj] * v1.w;
            }
        }

        // combine with coarser sub-levels
        const int r = (w << 4) + i;  // chunk-local finest row
        const float* y1r = s_y1 + (r >> 1) * SD + (dg << 5);
        const float* y2r = s_y2 + (r >> 2) * SD + (dg << 5);
#pragma unroll
        for (int cc = 0; cc < 8; cc++) {
            float4 u = *(const float4*)(y1r + cc * 4);
            float4 t2 = *(const float4*)(y2r + cc * 4);
            yacc[cc].x += u.x + t2.x;
            yacc[cc].y += u.y + t2.y;
            yacc[cc].z += u.z + t2.z;
            yacc[cc].w += u.w + t2.w;
        }
        float at = rs + s_a1[r >> 1] + s_a2[r >> 2];

        float* yst = s_q0 + r * SD + (dg << 5);
#pragma unroll
        for (int cc = 0; cc < 8; cc++) *(float4*)(yst + cc * 4) = yacc[cc];
        if (dg == 0) s_aS[r] = at;
    }
    __syncthreads();

    // ---- Phase 5: coalesced writeout ----
    float4* Yg = (float4*)(Yout + base);
    for (int idx = tid; idx < 2048; idx += 256) {
        int row = idx >> 4, c4 = (idx & 15) << 2;
        Yg[idx] = *(const float4*)(s_q0 + row * SD + c4);
    }
    if (tid < 128)
        Aout[(size_t)bh * (size_t)ntok + (size_t)c * 128 + tid] = s_aS[tid];
}

// ---------------------------------------------------------------------------
// Final combine: out[i] = (Y012[i] + Y345[i>>3] + Y678[i>>6]) / (sumA + eps)
// ---------------------------------------------------------------------------
__global__ __launch_bounds__(256)
void hatt_combine(float* __restrict__ out)
{
    unsigned idx = blockIdx.x * 256u + threadIdx.x;  // < 4194304 float4s
    unsigned f = idx & 15u;
    unsigned tok = (idx >> 4) & 8191u;
    unsigned bh = idx >> 17;

    float4 y = ((const float4*)g_Y012)[idx];
    float4 y3 = ((const float4*)g_Y345)[(((size_t)bh << 10) + (tok >> 3)) * 16 + f];
    float4 y6 = ((const float4*)g_Y678)[(((size_t)bh << 7) + (tok >> 6)) * 16 + f];
    float a = g_A012[((size_t)bh << 13) + tok]
            + g_A345[((size_t)bh << 10) + (tok >> 3)]
            + g_A678[((size_t)bh << 7) + (tok >> 6)] + 1e-8f;
    float inv = 1.0f / a;
    float4 o;
    o.x = (y.x + y3.x + y6.x) * inv;
    o.y = (y.y + y3.y + y6.y) * inv;
    o.z = (y.z + y3.z + y6.z) * inv;
    o.w = (y.w + y3.w + y6.w) * inv;
    ((float4*)out)[idx] = o;
}

// ---------------------------------------------------------------------------
extern "C" void kernel_launch(void* const* d_in, const int* in_sizes, int n_in,
                              void* d_out, int out_size)
{
    const float* q = (const float*)d_in[0];
    const float* k = (const float*)d_in[1];
    const float* v = (const float*)d_in[2];
    float* out = (float*)d_out;
    (void)in_sizes; (void)n_in; (void)out_size;

    void *Y012, *A012, *q3, *k3, *v3, *Y345, *A345, *q6, *k6, *v6, *Y678, *A678;
    cudaGetSymbolAddress(&Y012, g_Y012);
    cudaGetSymbolAddress(&A012, g_A012);
    cudaGetSymbolAddress(&q3, g_q3);
    cudaGetSymbolAddress(&k3, g_k3);
    cudaGetSymbolAddress(&v3, g_v3);
    cudaGetSymbolAddress(&Y345, g_Y345);
    cudaGetSymbolAddress(&A345, g_A345);
    cudaGetSymbolAddress(&q6, g_q6);
    cudaGetSymbolAddress(&k6, g_k6);
    cudaGetSymbolAddress(&v6, g_v6);
    cudaGetSymbolAddress(&Y678, g_Y678);
    cudaGetSymbolAddress(&A678, g_A678);

    const int smem = 52448 * (int)sizeof(float);  // 209792 bytes
    cudaFuncSetAttribute(hatt_tri<false, true>, cudaFuncAttributeMaxDynamicSharedMemorySize, smem);
    cudaFuncSetAttribute(hatt_tri<true, true>, cudaFuncAttributeMaxDynamicSharedMemorySize, smem);
    cudaFuncSetAttribute(hatt_tri<true, false>, cudaFuncAttributeMaxDynamicSharedMemorySize, smem);

    // Levels 0-2 on original tokens (level 0 = self-attention, no flip).
    hatt_tri<false, true><<<dim3(64, 32), 256, smem>>>(
        q, k, v, N0, 0.125f,
        (float*)Y012, (float*)A012, (float*)q3, (float*)k3, (float*)v3);

    // Levels 3-5 on pooled lvl3 (all sibling-flipped).
    hatt_tri<true, true><<<dim3(8, 32), 256, smem>>>(
        (const float*)q3, (const float*)k3, (const float*)v3, N0 / 8, 1.0f,
        (float*)Y345, (float*)A345, (float*)q6, (float*)k6, (float*)v6);

    // Levels 6-8 on pooled lvl6 (all sibling-flipped, no further pooling).
    hatt_tri<true, false><<<dim3(1, 32), 256, smem>>>(
        (const float*)q6, (const float*)k6, (const float*)v6, N0 / 64, 1.0f,
        (float*)Y678, (float*)A678, nullptr, nullptr, nullptr);

    // Final combine + divide.
    hatt_combine<<<4194304 / 256, 256>>>(out);
}

// round 4
// speedup vs baseline: 1.0721x; 1.0721x over previous
#include <cuda_runtime.h>

// ---------------------------------------------------------------------------
// HAttention1D: b=4 h=8 n=8192 d=64, block=16, 9 levels (0..8).
// Levels grouped in threes: K1 = levels 0-2 (+pool to lvl3),
// K2 = levels 3-5 (+pool to lvl6), K3 = levels 6-8, K4 = combine/divide.
// R3: 512 threads/CTA, concurrent warp roles, direct global Y writeout.
// ---------------------------------------------------------------------------

#define BHN 32
#define N0  8192
#define DD  64
#define SD  68   // padded smem row stride in floats (272B -> <=2-way conflicts)

// ---- scratch (device globals; no allocations allowed) ----
__device__ __align__(16) float g_Y012[(size_t)BHN * N0 * DD];        // 64 MB
__device__ __align__(16) float g_A012[BHN * N0];
__device__ __align__(16) float g_q3[BHN * (N0 / 8) * DD];            // 8 MB each
__device__ __align__(16) float g_k3[BHN * (N0 / 8) * DD];
__device__ __align__(16) float g_v3[BHN * (N0 / 8) * DD];
__device__ __align__(16) float g_Y345[BHN * (N0 / 8) * DD];
__device__ __align__(16) float g_A345[BHN * (N0 / 8)];
__device__ __align__(16) float g_q6[BHN * (N0 / 64) * DD];
__device__ __align__(16) float g_k6[BHN * (N0 / 64) * DD];
__device__ __align__(16) float g_v6[BHN * (N0 / 64) * DD];
__device__ __align__(16) float g_Y678[BHN * (N0 / 64) * DD];
__device__ __align__(16) float g_A678[BHN * (N0 / 64)];

// ---- float4 helpers ----
__device__ __forceinline__ float4 f4_add(float4 a, float4 b) {
    return make_float4(a.x + b.x, a.y + b.y, a.z + b.z, a.w + b.w);
}
__device__ __forceinline__ float4 f4_avg(float4 a, float4 b) {
    return make_float4((a.x + b.x) * 0.5f, (a.y + b.y) * 0.5f,
                       (a.z + b.z) * 0.5f, (a.w + b.w) * 0.5f);
}
__device__ __forceinline__ float4 f4_scale(float4 a, float s) {
    return make_float4(a.x * s, a.y * s, a.z * s, a.w * s);
}

// ---------------------------------------------------------------------------
// One warp computes a full 16x16 block attention (S = qb@kb^T, rowmax, exp,
// y = A@vb, a = rowsum(A)) and writes y (16 x 64, stride SD) + a to smem.
// Lane mapping: i = lane&15 (query row), jh = lane>>4 (key-column half).
// ---------------------------------------------------------------------------
__device__ __forceinline__ void attn16_smem(const float* __restrict__ qB,
                                            const float* __restrict__ kB,
                                            const float* __restrict__ vB,
                                            float* __restrict__ yOut,
                                            float* __restrict__ aOut,
                                            int lane)
{
    const int i = lane & 15;
    const int jh = lane >> 4;
    const float* qr = qB + i * SD;
    const float* kr = kB + jh * 8 * SD;

    float acc[8];
#pragma unroll
    for (int jj = 0; jj < 8; jj++) acc[jj] = 0.f;

#pragma unroll
    for (int c4 = 0; c4 < 16; c4++) {
        float4 qv = *(const float4*)(qr + c4 * 4);
#pragma unroll
        for (int jj = 0; jj < 8; jj++) {
            float4 kv = *(const float4*)(kr + jj * SD + c4 * 4);
            acc[jj] += qv.x * kv.x + qv.y * kv.y + qv.z * kv.z + qv.w * kv.w;
        }
    }

    float m = acc[0];
#pragma unroll
    for (int jj = 1; jj < 8; jj++) m = fmaxf(m, acc[jj]);
    m = fmaxf(m, __shfl_xor_sync(0xffffffffu, m, 16));

    float A[8];
    float rs = 0.f;
#pragma unroll
    for (int jj = 0; jj < 8; jj++) { A[jj] = __expf(acc[jj] - m); rs += A[jj]; }
    rs += __shfl_xor_sync(0xffffffffu, rs, 16);
    if (jh == 0) aOut[i] = rs;

    const float* vr = vB + jh * 8 * SD;
#pragma unroll
    for (int c4 = 0; c4 < 16; c4++) {
        float yx = 0.f, yy = 0.f, yz = 0.f, yw = 0.f;
#pragma unroll
        for (int jj = 0; jj < 8; jj++) {
            float4 vv = *(const float4*)(vr + jj * SD + c4 * 4);
            yx += A[jj] * vv.x; yy += A[jj] * vv.y;
            yz += A[jj] * vv.z; yw += A[jj] * vv.w;
        }
        yx += __shfl_xor_sync(0xffffffffu, yx, 16);
        yy += __shfl_xor_sync(0xffffffffu, yy, 16);
        yz += __shfl_xor_sync(0xffffffffu, yz, 16);
        yw += __shfl_xor_sync(0xffffffffu, yw, 16);
        if (jh == 0) *(float4*)(yOut + i * SD + c4 * 4) = make_float4(yx, yy, yz, yw);
    }
}

// ---------------------------------------------------------------------------
// Tri-level kernel, 512 threads. Chunk of 128 tokens at this kernel's finest
// sub-level. Computes 3 consecutive levels, writes combined Y (=y0+y1+y2 at
// finest resolution) + combined A, and (optionally) pools to the next
// tri-level. FLIP0: does sub-level 0 use the sibling block?
// ---------------------------------------------------------------------------
template <bool FLIP0, bool POOL>
__global__ __launch_bounds__(512, 1)
void hatt_tri(const float* __restrict__ Q, const float* __restrict__ K,
              const float* __restrict__ V, int ntok, float qscale,
              float* __restrict__ Yout, float* __restrict__ Aout,
              float* __restrict__ Qp, float* __restrict__ Kp,
              float* __restrict__ Vp)
{
    extern __shared__ float sm[];
    float* s_q0 = sm;                    // 128*SD
    float* s_k0 = s_q0 + 128 * SD;       // 128*SD
    float* s_v0 = s_k0 + 128 * SD;       // 128*SD
    float* s_q1 = s_v0 + 128 * SD;       // 64*SD
    float* s_k1 = s_q1 + 64 * SD;
    float* s_v1 = s_k1 + 64 * SD;
    float* s_q2 = s_v1 + 64 * SD;        // 32*SD
    float* s_k2 = s_q2 + 32 * SD;
    float* s_v2 = s_k2 + 32 * SD;
    float* s_y1 = s_v2 + 32 * SD;        // 64*SD
    float* s_y2 = s_y1 + 64 * SD;        // 32*SD
    float* s_a1 = s_y2 + 32 * SD;        // 64
    float* s_a2 = s_a1 + 64;             // 32

    const int tid = threadIdx.x;
    const int bh = blockIdx.y;
    const int c = blockIdx.x;
    const size_t base = ((size_t)bh * (size_t)ntok + (size_t)c * 128) * DD;

    // ---- Phase 1: load chunk (q scaled) ----
    const float4* qg = (const float4*)(Q + base);
    const float4* kg = (const float4*)(K + base);
    const float4* vg = (const float4*)(V + base);
    for (int idx = tid; idx < 2048; idx += 512) {
        int row = idx >> 4, c4 = (idx & 15) << 2;
        float4 a = qg[idx];
        a.x *= qscale; a.y *= qscale; a.z *= qscale; a.w *= qscale;
        *(float4*)(s_q0 + row * SD + c4) = a;
        *(float4*)(s_k0 + row * SD + c4) = kg[idx];
        *(float4*)(s_v0 + row * SD + c4) = vg[idx];
    }
    __syncthreads();

    // ---- Phase 2: pool lvl1 (pairs) and lvl2 (quads) from lvl0, one pass ----
    for (int idx = tid; idx < 1536; idx += 512) {
        if (idx < 1024) {
            int t = idx >> 4, c4 = (idx & 15) << 2;
            int r0 = (2 * t) * SD + c4, r1 = (2 * t + 1) * SD + c4, rd = t * SD + c4;
            *(float4*)(s_q1 + rd) = f4_avg(*(const float4*)(s_q0 + r0), *(const float4*)(s_q0 + r1));
            *(float4*)(s_k1 + rd) = f4_avg(*(const float4*)(s_k0 + r0), *(const float4*)(s_k0 + r1));
            *(float4*)(s_v1 + rd) = f4_add(*(const float4*)(s_v0 + r0), *(const float4*)(s_v0 + r1));
        } else {
            int j = idx - 1024;
            int t = j >> 4, c4 = (j & 15) << 2;
            int rd = t * SD + c4;
            float4 qs = make_float4(0.f, 0.f, 0.f, 0.f), ks = qs, vs = qs;
#pragma unroll
            for (int p = 0; p < 4; p++) {
                int r = (4 * t + p) * SD + c4;
                qs = f4_add(qs, *(const float4*)(s_q0 + r));
                ks = f4_add(ks, *(const float4*)(s_k0 + r));
                vs = f4_add(vs, *(const float4*)(s_v0 + r));
            }
            *(float4*)(s_q2 + rd) = f4_scale(qs, 0.25f);
            *(float4*)(s_k2 + rd) = f4_scale(ks, 0.25f);
            *(float4*)(s_v2 + rd) = vs;
        }
    }
    __syncthreads();

    const int w = tid >> 5;
    const int lane = tid & 31;
    const int i = lane & 15;
    const int dg = lane >> 4;

    // ---- Phase 3 (concurrent warp roles) ----
    //  w 0-7 : level-0 S + softmax (needs q0,k0 only); keep A row in regs
    //  w 8-11: level-1 attention (4 blocks, sibling flip) -> s_y1/s_a1
    //  w12-13: level-2 attention (2 blocks, sibling flip) -> s_y2/s_a2
    //  w14-15: pool to next tri-level (global write), if POOL
    float Af0[8], Af1[8];   // full 16-wide A row (cols 0-7 / 8-15), w<8 only
    float rs = 0.f;
    int sb0 = FLIP0 ? (w ^ 1) : w;

    if (w < 8) {
        const float* qr = s_q0 + (w * 16 + i) * SD;
        const float* kr = s_k0 + (sb0 * 16 + dg * 8) * SD;
        float acc[8];
#pragma unroll
        for (int jj = 0; jj < 8; jj++) acc[jj] = 0.f;
#pragma unroll
        for (int c4 = 0; c4 < 16; c4++) {
            float4 qv = *(const float4*)(qr + c4 * 4);
#pragma unroll
            for (int jj = 0; jj < 8; jj++) {
                float4 kv = *(const float4*)(kr + jj * SD + c4 * 4);
                acc[jj] += qv.x * kv.x + qv.y * kv.y + qv.z * kv.z + qv.w * kv.w;
            }
        }
        float m = acc[0];
#pragma unroll
        for (int jj = 1; jj < 8; jj++) m = fmaxf(m, acc[jj]);
        m = fmaxf(m, __shfl_xor_sync(0xffffffffu, m, 16));
        float A[8];
#pragma unroll
        for (int jj = 0; jj < 8; jj++) { A[jj] = __expf(acc[jj] - m); rs += A[jj]; }
        rs += __shfl_xor_sync(0xffffffffu, rs, 16);  // full row sum, both halves
        // exchange halves so every lane holds the full 16-wide A row
#pragma unroll
        for (int jj = 0; jj < 8; jj++) {
            float o = __shfl_xor_sync(0xffffffffu, A[jj], 16);
            Af0[jj] = dg ? o : A[jj];
            Af1[jj] = dg ? A[jj] : o;
        }
    } else if (w < 12) {
        int qb = w - 8, sb = qb ^ 1;
        attn16_smem(s_q1 + qb * 16 * SD, s_k1 + sb * 16 * SD, s_v1 + sb * 16 * SD,
                    s_y1 + qb * 16 * SD, s_a1 + qb * 16, lane);
    } else if (w < 14) {
        int qb = w - 12, sb = qb ^ 1;
        attn16_smem(s_q2 + qb * 16 * SD, s_k2 + sb * 16 * SD, s_v2 + sb * 16 * SD,
                    s_y2 + qb * 16 * SD, s_a2 + qb * 16, lane);
    } else if (POOL) {
        int t2 = tid - 448;  // 0..63
        for (int idx = t2; idx < 256; idx += 64) {
            int t = idx >> 4, c4 = (idx & 15) << 2;
            int r0 = (2 * t) * SD + c4, r1 = (2 * t + 1) * SD + c4;
            size_t gi = ((size_t)bh * (size_t)(ntok >> 3) + (size_t)(c * 16 + t)) * DD + c4;
            *(float4*)(Qp + gi) = f4_avg(*(const float4*)(s_q2 + r0), *(const float4*)(s_q2 + r1));
            *(float4*)(Kp + gi) = f4_avg(*(const float4*)(s_k2 + r0), *(const float4*)(s_k2 + r1));
            *(float4*)(Vp + gi) = f4_add(*(const float4*)(s_v2 + r0), *(const float4*)(s_v2 + r1));
        }
    }
    __syncthreads();

    // ---- Phase 4 (w 0-7): y = A@v0, combine with y1/y2, direct global write.
    //      Lane covers dims [dg*32, dg*32+32) of row r = w*16+i.
    if (w < 8) {
        const float* vB = s_v0 + sb0 * 16 * SD;
        float4 yacc[8];
#pragma unroll
        for (int cc = 0; cc < 8; cc++) yacc[cc] = make_float4(0.f, 0.f, 0.f, 0.f);
#pragma unroll
        for (int jj = 0; jj < 8; jj++) {
            const float* vr0 = vB + jj * SD + (dg << 5);
            const float* vr1 = vB + (8 + jj) * SD + (dg << 5);
#pragma unroll
            for (int cc = 0; cc < 8; cc++) {
                float4 v0 = *(const float4*)(vr0 + cc * 4);
                float4 v1 = *(const float4*)(vr1 + cc * 4);
                yacc[cc].x += Af0[jj] * v0.x + Af1[jj] * v1.x;
                yacc[cc].y += Af0[jj] * v0.y + Af1[jj] * v1.y;
                yacc[cc].z += Af0[jj] * v0.z + Af1[jj] * v1.z;
                yacc[cc].w += Af0[jj] * v0.w + Af1[jj] * v1.w;
            }
        }
        const int r = (w << 4) + i;
        const float* y1r = s_y1 + (r >> 1) * SD + (dg << 5);
        const float* y2r = s_y2 + (r >> 2) * SD + (dg << 5);
        float* yg = Yout + base + r * DD + (dg << 5);
#pragma unroll
        for (int cc = 0; cc < 8; cc++) {
            float4 u = *(const float4*)(y1r + cc * 4);
            float4 t2 = *(const float4*)(y2r + cc * 4);
            yacc[cc].x += u.x + t2.x;
            yacc[cc].y += u.y + t2.y;
            yacc[cc].z += u.z + t2.z;
            yacc[cc].w += u.w + t2.w;
            *(float4*)(yg + cc * 4) = yacc[cc];
        }
        if (dg == 0)
            Aout[(size_t)bh * (size_t)ntok + (size_t)c * 128 + r]
                = rs + s_a1[r >> 1] + s_a2[r >> 2];
    }
}

// ---------------------------------------------------------------------------
// Final combine: out[i] = (Y012[i] + Y345[i>>3] + Y678[i>>6]) / (sumA + eps)
// ---------------------------------------------------------------------------
__global__ __launch_bounds__(256)
void hatt_combine(float* __restrict__ out)
{
    unsigned idx = blockIdx.x * 256u + threadIdx.x;  // < 4194304 float4s
    unsigned f = idx & 15u;
    unsigned tok = (idx >> 4) & 8191u;
    unsigned bh = idx >> 17;

    float4 y = ((const float4*)g_Y012)[idx];
    float4 y3 = ((const float4*)g_Y345)[(((size_t)bh << 10) + (tok >> 3)) * 16 + f];
    float4 y6 = ((const float4*)g_Y678)[(((size_t)bh << 7) + (tok >> 6)) * 16 + f];
    float a = g_A012[((size_t)bh << 13) + tok]
            + g_A345[((size_t)bh << 10) + (tok >> 3)]
            + g_A678[((size_t)bh << 7) + (tok >> 6)] + 1e-8f;
    float inv = 1.0f / a;
    float4 o;
    o.x = (y.x + y3.x + y6.x) * inv;
    o.y = (y.y + y3.y + y6.y) * inv;
    o.z = (y.z + y3.z + y6.z) * inv;
    o.w = (y.w + y3.w + y6.w) * inv;
    ((float4*)out)[idx] = o;
}

// ---------------------------------------------------------------------------
extern "C" void kernel_launch(void* const* d_in, const int* in_sizes, int n_in,
                              void* d_out, int out_size)
{
    const float* q = (const float*)d_in[0];
    const float* k = (const float*)d_in[1];
    const float* v = (const float*)d_in[2];
    float* out = (float*)d_out;
    (void)in_sizes; (void)n_in; (void)out_size;

    void *Y012, *A012, *q3, *k3, *v3, *Y345, *A345, *q6, *k6, *v6, *Y678, *A678;
    cudaGetSymbolAddress(&Y012, g_Y012);
    cudaGetSymbolAddress(&A012, g_A012);
    cudaGetSymbolAddress(&q3, g_q3);
    cudaGetSymbolAddress(&k3, g_k3);
    cudaGetSymbolAddress(&v3, g_v3);
    cudaGetSymbolAddress(&Y345, g_Y345);
    cudaGetSymbolAddress(&A345, g_A345);
    cudaGetSymbolAddress(&q6, g_q6);
    cudaGetSymbolAddress(&k6, g_k6);
    cudaGetSymbolAddress(&v6, g_v6);
    cudaGetSymbolAddress(&Y678, g_Y678);
    cudaGetSymbolAddress(&A678, g_A678);

    const int smem = 52448 * (int)sizeof(float);  // 209792 bytes
    cudaFuncSetAttribute(hatt_tri<false, true>, cudaFuncAttributeMaxDynamicSharedMemorySize, smem);
    cudaFuncSetAttribute(hatt_tri<true, true>, cudaFuncAttributeMaxDynamicSharedMemorySize, smem);
    cudaFuncSetAttribute(hatt_tri<true, false>, cudaFuncAttributeMaxDynamicSharedMemorySize, smem);

    // Levels 0-2 on original tokens (level 0 = self-attention, no flip).
    hatt_tri<false, true><<<dim3(64, 32), 512, smem>>>(
        q, k, v, N0, 0.125f,
        (float*)Y012, (float*)A012, (float*)q3, (float*)k3, (float*)v3);

    // Levels 3-5 on pooled lvl3 (all sibling-flipped).
    hatt_tri<true, true><<<dim3(8, 32), 512, smem>>>(
        (const float*)q3, (const float*)k3, (const float*)v3, N0 / 8, 1.0f,
        (float*)Y345, (float*)A345, (float*)q6, (float*)k6, (float*)v6);

    // Levels 6-8 on pooled lvl6 (all sibling-flipped, no further pooling).
    hatt_tri<true, false><<<dim3(1, 32), 512, smem>>>(
        (const float*)q6, (const float*)k6, (const float*)v6, N0 / 64, 1.0f,
        (float*)Y678, (float*)A678, nullptr, nullptr, nullptr);

    // Final combine + divide.
    hatt_combine<<<4194304 / 256, 256>>>(out);
}

// round 5
// speedup vs baseline: 1.2457x; 1.1619x over previous
#include <cuda_runtime.h>

// ---------------------------------------------------------------------------
// HAttention1D: b=4 h=8 n=8192 d=64, block=16, 9 levels (0..8).
// Levels grouped in threes: K1 = levels 0-2 (+pool to lvl3),
// K2 = levels 3-5 (+pool to lvl6), K3 = levels 6-8, K4 = combine/divide.
// R4: symmetric two-phase schedule — all 14 blocks do S in phase A
//     (balanced), shuffle-free d-split y in phase B. No attn16_smem.
// ---------------------------------------------------------------------------

#define BHN 32
#define N0  8192
#define DD  64
#define SD  68   // padded smem row stride in floats

// ---- scratch (device globals; no allocations allowed) ----
__device__ __align__(16) float g_Y012[(size_t)BHN * N0 * DD];        // 64 MB
__device__ __align__(16) float g_A012[BHN * N0];
__device__ __align__(16) float g_q3[BHN * (N0 / 8) * DD];            // 8 MB each
__device__ __align__(16) float g_k3[BHN * (N0 / 8) * DD];
__device__ __align__(16) float g_v3[BHN * (N0 / 8) * DD];
__device__ __align__(16) float g_Y345[BHN * (N0 / 8) * DD];
__device__ __align__(16) float g_A345[BHN * (N0 / 8)];
__device__ __align__(16) float g_q6[BHN * (N0 / 64) * DD];
__device__ __align__(16) float g_k6[BHN * (N0 / 64) * DD];
__device__ __align__(16) float g_v6[BHN * (N0 / 64) * DD];
__device__ __align__(16) float g_Y678[BHN * (N0 / 64) * DD];
__device__ __align__(16) float g_A678[BHN * (N0 / 64)];

// ---- float4 helpers ----
__device__ __forceinline__ float4 f4_add(float4 a, float4 b) {
    return make_float4(a.x + b.x, a.y + b.y, a.z + b.z, a.w + b.w);
}
__device__ __forceinline__ float4 f4_avg(float4 a, float4 b) {
    return make_float4((a.x + b.x) * 0.5f, (a.y + b.y) * 0.5f,
                       (a.z + b.z) * 0.5f, (a.w + b.w) * 0.5f);
}
__device__ __forceinline__ float4 f4_scale(float4 a, float s) {
    return make_float4(a.x * s, a.y * s, a.z * s, a.w * s);
}

// ---------------------------------------------------------------------------
// Tri-level kernel, 512 threads. Chunk of 128 tokens at this kernel's finest
// sub-level. Computes 3 consecutive levels, writes combined Y (=y0+y1+y2 at
// finest resolution) + combined A, and (optionally) pools to the next
// tri-level. FLIP0: does sub-level 0 use the sibling block?
//
// Warp roles (14 attention blocks total):
//   w 0-7 : level-0 block w          (sibling = w^1 if FLIP0 else w)
//   w 8-11: level-1 block w-8        (sibling flip)
//   w12-13: level-2 block w-12       (sibling flip)
//   w14-15: pool to next tri-level (global write), if POOL
// Phase A: S + softmax for all 14 blocks (balanced). Phase B: shuffle-free
// d-split y for all 14 blocks. Phase C: lvl0 warps combine + global write.
// ---------------------------------------------------------------------------
template <bool FLIP0, bool POOL>
__global__ __launch_bounds__(512, 1)
void hatt_tri(const float* __restrict__ Q, const float* __restrict__ K,
              const float* __restrict__ V, int ntok, float qscale,
              float* __restrict__ Yout, float* __restrict__ Aout,
              float* __restrict__ Qp, float* __restrict__ Kp,
              float* __restrict__ Vp)
{
    extern __shared__ float sm[];
    float* s_q0 = sm;                    // 128*SD
    float* s_k0 = s_q0 + 128 * SD;       // 128*SD
    float* s_v0 = s_k0 + 128 * SD;       // 128*SD
    float* s_q1 = s_v0 + 128 * SD;       // 64*SD
    float* s_k1 = s_q1 + 64 * SD;
    float* s_v1 = s_k1 + 64 * SD;
    float* s_q2 = s_v1 + 64 * SD;        // 32*SD
    float* s_k2 = s_q2 + 32 * SD;
    float* s_v2 = s_k2 + 32 * SD;
    float* s_y1 = s_v2 + 32 * SD;        // 64*SD
    float* s_y2 = s_y1 + 64 * SD;        // 32*SD
    float* s_a1 = s_y2 + 32 * SD;        // 64
    float* s_a2 = s_a1 + 64;             // 32

    const int tid = threadIdx.x;
    const int bh = blockIdx.y;
    const int c = blockIdx.x;
    const size_t base = ((size_t)bh * (size_t)ntok + (size_t)c * 128) * DD;

    // ---- Phase 1: load chunk (q scaled); batch 12 LDG.128 for MLP ----
    {
        const float4* qg = (const float4*)(Q + base);
        const float4* kg = (const float4*)(K + base);
        const float4* vg = (const float4*)(V + base);
        float4 rq[4], rk[4], rv[4];
#pragma unroll
        for (int it = 0; it < 4; it++) {
            int idx = tid + it * 512;
            rq[it] = qg[idx]; rk[it] = kg[idx]; rv[it] = vg[idx];
        }
#pragma unroll
        for (int it = 0; it < 4; it++) {
            int idx = tid + it * 512;
            int row = idx >> 4, c4 = (idx & 15) << 2;
            *(float4*)(s_q0 + row * SD + c4) = f4_scale(rq[it], qscale);
            *(float4*)(s_k0 + row * SD + c4) = rk[it];
            *(float4*)(s_v0 + row * SD + c4) = rv[it];
        }
    }
    __syncthreads();

    // ---- Phase 2: pool lvl1 (pairs) and lvl2 (quads) from lvl0, one pass ----
    for (int idx = tid; idx < 1536; idx += 512) {
        if (idx < 1024) {
            int t = idx >> 4, c4 = (idx & 15) << 2;
            int r0 = (2 * t) * SD + c4, r1 = (2 * t + 1) * SD + c4, rd = t * SD + c4;
            *(float4*)(s_q1 + rd) = f4_avg(*(const float4*)(s_q0 + r0), *(const float4*)(s_q0 + r1));
            *(float4*)(s_k1 + rd) = f4_avg(*(const float4*)(s_k0 + r0), *(const float4*)(s_k0 + r1));
            *(float4*)(s_v1 + rd) = f4_add(*(const float4*)(s_v0 + r0), *(const float4*)(s_v0 + r1));
        } else {
            int j = idx - 1024;
            int t = j >> 4, c4 = (j & 15) << 2;
            int rd = t * SD + c4;
            float4 qs = make_float4(0.f, 0.f, 0.f, 0.f), ks = qs, vs = qs;
#pragma unroll
            for (int p = 0; p < 4; p++) {
                int r = (4 * t + p) * SD + c4;
                qs = f4_add(qs, *(const float4*)(s_q0 + r));
                ks = f4_add(ks, *(const float4*)(s_k0 + r));
                vs = f4_add(vs, *(const float4*)(s_v0 + r));
            }
            *(float4*)(s_q2 + rd) = f4_scale(qs, 0.25f);
            *(float4*)(s_k2 + rd) = f4_scale(ks, 0.25f);
            *(float4*)(s_v2 + rd) = vs;
        }
    }
    __syncthreads();

    const int w = tid >> 5;
    const int lane = tid & 31;
    const int i = lane & 15;
    const int dg = lane >> 4;

    // ---- Role pointers ----
    const float* qB = nullptr;
    const float* kB = nullptr;
    const float* vB = nullptr;
    float* yB = nullptr;     // smem y target (lvl1/lvl2 only)
    float* aB = nullptr;
    if (w < 8) {
        int sb = FLIP0 ? (w ^ 1) : w;
        qB = s_q0 + w * 16 * SD;
        kB = s_k0 + sb * 16 * SD;
        vB = s_v0 + sb * 16 * SD;
    } else if (w < 12) {
        int qb = w - 8, sb = qb ^ 1;
        qB = s_q1 + qb * 16 * SD;
        kB = s_k1 + sb * 16 * SD;
        vB = s_v1 + sb * 16 * SD;
        yB = s_y1 + qb * 16 * SD;
        aB = s_a1 + qb * 16;
    } else if (w < 14) {
        int qb = w - 12, sb = qb ^ 1;
        qB = s_q2 + qb * 16 * SD;
        kB = s_k2 + sb * 16 * SD;
        vB = s_v2 + sb * 16 * SD;
        yB = s_y2 + qb * 16 * SD;
        aB = s_a2 + qb * 16;
    }

    // ---- Phase A: S + softmax for all 14 blocks (w14/15: pool) ----
    float Af0[8], Af1[8];   // full 16-wide A row (cols 0-7 / 8-15)
    float rs = 0.f;
    if (w < 14) {
        const float* qr = qB + i * SD;
        const float* kr = kB + dg * 8 * SD;
        float acc[8];
#pragma unroll
        for (int jj = 0; jj < 8; jj++) acc[jj] = 0.f;
#pragma unroll
        for (int c4 = 0; c4 < 16; c4++) {
            float4 qv = *(const float4*)(qr + c4 * 4);
#pragma unroll
            for (int jj = 0; jj < 8; jj++) {
                float4 kv = *(const float4*)(kr + jj * SD + c4 * 4);
                acc[jj] += qv.x * kv.x + qv.y * kv.y + qv.z * kv.z + qv.w * kv.w;
            }
        }
        float m = acc[0];
#pragma unroll
        for (int jj = 1; jj < 8; jj++) m = fmaxf(m, acc[jj]);
        m = fmaxf(m, __shfl_xor_sync(0xffffffffu, m, 16));
        float A[8];
#pragma unroll
        for (int jj = 0; jj < 8; jj++) { A[jj] = __expf(acc[jj] - m); rs += A[jj]; }
        rs += __shfl_xor_sync(0xffffffffu, rs, 16);  // full row sum, both halves
        // exchange halves so every lane holds the full 16-wide A row
#pragma unroll
        for (int jj = 0; jj < 8; jj++) {
            float o = __shfl_xor_sync(0xffffffffu, A[jj], 16);
            Af0[jj] = dg ? o : A[jj];
            Af1[jj] = dg ? A[jj] : o;
        }
    } else if (POOL) {
        int t2 = tid - 448;  // 0..63
        for (int idx = t2; idx < 256; idx += 64) {
            int t = idx >> 4, c4 = (idx & 15) << 2;
            int r0 = (2 * t) * SD + c4, r1 = (2 * t + 1) * SD + c4;
            size_t gi = ((size_t)bh * (size_t)(ntok >> 3) + (size_t)(c * 16 + t)) * DD + c4;
            *(float4*)(Qp + gi) = f4_avg(*(const float4*)(s_q2 + r0), *(const float4*)(s_q2 + r1));
            *(float4*)(Kp + gi) = f4_avg(*(const float4*)(s_k2 + r0), *(const float4*)(s_k2 + r1));
            *(float4*)(Vp + gi) = f4_add(*(const float4*)(s_v2 + r0), *(const float4*)(s_v2 + r1));
        }
    }
    __syncthreads();

    // ---- Phase B: shuffle-free d-split y for all 14 blocks.
    //      Lane covers dims [dg*32, dg*32+32) of its block's row i.
    float4 yacc[8];
    if (w < 14) {
#pragma unroll
        for (int cc = 0; cc < 8; cc++) yacc[cc] = make_float4(0.f, 0.f, 0.f, 0.f);
#pragma unroll
        for (int jj = 0; jj < 8; jj++) {
            const float* vr0 = vB + jj * SD + (dg << 5);
            const float* vr1 = vB + (8 + jj) * SD + (dg << 5);
#pragma unroll
            for (int cc = 0; cc < 8; cc++) {
                float4 v0 = *(const float4*)(vr0 + cc * 4);
                float4 v1 = *(const float4*)(vr1 + cc * 4);
                yacc[cc].x += Af0[jj] * v0.x + Af1[jj] * v1.x;
                yacc[cc].y += Af0[jj] * v0.y + Af1[jj] * v1.y;
                yacc[cc].z += Af0[jj] * v0.z + Af1[jj] * v1.z;
                yacc[cc].w += Af0[jj] * v0.w + Af1[jj] * v1.w;
            }
        }
        if (w >= 8) {   // lvl1/lvl2: stage into smem
            float* yo = yB + i * SD + (dg << 5);
#pragma unroll
            for (int cc = 0; cc < 8; cc++) *(float4*)(yo + cc * 4) = yacc[cc];
            if (dg == 0) aB[i] = rs;
        }
    }
    __syncthreads();

    // ---- Phase C (w 0-7): combine with y1/y2, direct global write ----
    if (w < 8) {
        const int r = (w << 4) + i;
        const float* y1r = s_y1 + (r >> 1) * SD + (dg << 5);
        const float* y2r = s_y2 + (r >> 2) * SD + (dg << 5);
        float* yg = Yout + base + r * DD + (dg << 5);
#pragma unroll
        for (int cc = 0; cc < 8; cc++) {
            float4 u = *(const float4*)(y1r + cc * 4);
            float4 t2 = *(const float4*)(y2r + cc * 4);
            yacc[cc].x += u.x + t2.x;
            yacc[cc].y += u.y + t2.y;
            yacc[cc].z += u.z + t2.z;
            yacc[cc].w += u.w + t2.w;
            *(float4*)(yg + cc * 4) = yacc[cc];
        }
        if (dg == 0)
            Aout[(size_t)bh * (size_t)ntok + (size_t)c * 128 + r]
                = rs + s_a1[r >> 1] + s_a2[r >> 2];
    }
}

// ---------------------------------------------------------------------------
// Final combine: out[i] = (Y012[i] + Y345[i>>3] + Y678[i>>6]) / (sumA + eps)
// ---------------------------------------------------------------------------
__global__ __launch_bounds__(256)
void hatt_combine(float* __restrict__ out)
{
    unsigned idx = blockIdx.x * 256u + threadIdx.x;  // < 4194304 float4s
    unsigned f = idx & 15u;
    unsigned tok = (idx >> 4) & 8191u;
    unsigned bh = idx >> 17;

    float4 y = ((const float4*)g_Y012)[idx];
    float4 y3 = ((const float4*)g_Y345)[(((size_t)bh << 10) + (tok >> 3)) * 16 + f];
    float4 y6 = ((const float4*)g_Y678)[(((size_t)bh << 7) + (tok >> 6)) * 16 + f];
    float a = g_A012[((size_t)bh << 13) + tok]
            + g_A345[((size_t)bh << 10) + (tok >> 3)]
            + g_A678[((size_t)bh << 7) + (tok >> 6)] + 1e-8f;
    float inv = 1.0f / a;
    float4 o;
    o.x = (y.x + y3.x + y6.x) * inv;
    o.y = (y.y + y3.y + y6.y) * inv;
    o.z = (y.z + y3.z + y6.z) * inv;
    o.w = (y.w + y3.w + y6.w) * inv;
    ((float4*)out)[idx] = o;
}

// ---------------------------------------------------------------------------
extern "C" void kernel_launch(void* const* d_in, const int* in_sizes, int n_in,
                              void* d_out, int out_size)
{
    const float* q = (const float*)d_in[0];
    const float* k = (const float*)d_in[1];
    const float* v = (const float*)d_in[2];
    float* out = (float*)d_out;
    (void)in_sizes; (void)n_in; (void)out_size;

    void *Y012, *A012, *q3, *k3, *v3, *Y345, *A345, *q6, *k6, *v6, *Y678, *A678;
    cudaGetSymbolAddress(&Y012, g_Y012);
    cudaGetSymbolAddress(&A012, g_A012);
    cudaGetSymbolAddress(&q3, g_q3);
    cudaGetSymbolAddress(&k3, g_k3);
    cudaGetSymbolAddress(&v3, g_v3);
    cudaGetSymbolAddress(&Y345, g_Y345);
    cudaGetSymbolAddress(&A345, g_A345);
    cudaGetSymbolAddress(&q6, g_q6);
    cudaGetSymbolAddress(&k6, g_k6);
    cudaGetSymbolAddress(&v6, g_v6);
    cudaGetSymbolAddress(&Y678, g_Y678);
    cudaGetSymbolAddress(&A678, g_A678);

    const int smem = 52448 * (int)sizeof(float);  // 209792 bytes
    cudaFuncSetAttribute(hatt_tri<false, true>, cudaFuncAttributeMaxDynamicSharedMemorySize, smem);
    cudaFuncSetAttribute(hatt_tri<true, true>, cudaFuncAttributeMaxDynamicSharedMemorySize, smem);
    cudaFuncSetAttribute(hatt_tri<true, false>, cudaFuncAttributeMaxDynamicSharedMemorySize, smem);

    // Levels 0-2 on original tokens (level 0 = self-attention, no flip).
    hatt_tri<false, true><<<dim3(64, 32), 512, smem>>>(
        q, k, v, N0, 0.125f,
        (float*)Y012, (float*)A012, (float*)q3, (float*)k3, (float*)v3);

    // Levels 3-5 on pooled lvl3 (all sibling-flipped).
    hatt_tri<true, true><<<dim3(8, 32), 512, smem>>>(
        (const float*)q3, (const float*)k3, (const float*)v3, N0 / 8, 1.0f,
        (float*)Y345, (float*)A345, (float*)q6, (float*)k6, (float*)v6);

    // Levels 6-8 on pooled lvl6 (all sibling-flipped, no further pooling).
    hatt_tri<true, false><<<dim3(1, 32), 512, smem>>>(
        (const float*)q6, (const float*)k6, (const float*)v6, N0 / 64, 1.0f,
        (float*)Y678, (float*)A678, nullptr, nullptr, nullptr);

    // Final combine + divide.
    hatt_combine<<<4194304 / 256, 256>>>(out);
}

// round 6
// speedup vs baseline: 1.2932x; 1.0382x over previous
#include <cuda_runtime.h>

// ---------------------------------------------------------------------------
// HAttention1D: b=4 h=8 n=8192 d=64, block=16, 9 levels (0..8).
// Levels grouped in threes: K1 = levels 0-2 (+pool to lvl3),
// K2 = levels 3-5 (+pool to lvl6), K3 = levels 6-8, K4 = combine/divide.
// R5: packed fp32x2 (fma.rn.f32x2) in both matmul loops + pooling — halves
//     FMA-pipe issue count, which R4 analysis showed is the binding pipe.
// ---------------------------------------------------------------------------

#define BHN 32
#define N0  8192
#define DD  64
#define SD  68   // padded smem row stride in floats

typedef unsigned long long u64;

// ---- packed f32x2 helpers ----
__device__ __forceinline__ u64 pk2(float a, float b) {
    u64 r; asm("mov.b64 %0, {%1, %2};" : "=l"(r) : "f"(a), "f"(b)); return r;
}
__device__ __forceinline__ void up2(u64 v, float& a, float& b) {
    asm("mov.b64 {%0, %1}, %2;" : "=f"(a), "=f"(b) : "l"(v));
}
__device__ __forceinline__ u64 fma2(u64 a, u64 b, u64 c) {
    u64 r; asm("fma.rn.f32x2 %0, %1, %2, %3;" : "=l"(r) : "l"(a), "l"(b), "l"(c)); return r;
}
__device__ __forceinline__ u64 add2(u64 a, u64 b) {
    u64 r; asm("add.rn.f32x2 %0, %1, %2;" : "=l"(r) : "l"(a), "l"(b)); return r;
}
__device__ __forceinline__ u64 mul2(u64 a, u64 b) {
    u64 r; asm("mul.rn.f32x2 %0, %1, %2;" : "=l"(r) : "l"(a), "l"(b)); return r;
}

// ---- scratch (device globals; no allocations allowed) ----
__device__ __align__(16) float g_Y012[(size_t)BHN * N0 * DD];        // 64 MB
__device__ __align__(16) float g_A012[BHN * N0];
__device__ __align__(16) float g_q3[BHN * (N0 / 8) * DD];            // 8 MB each
__device__ __align__(16) float g_k3[BHN * (N0 / 8) * DD];
__device__ __align__(16) float g_v3[BHN * (N0 / 8) * DD];
__device__ __align__(16) float g_Y345[BHN * (N0 / 8) * DD];
__device__ __align__(16) float g_A345[BHN * (N0 / 8)];
__device__ __align__(16) float g_q6[BHN * (N0 / 64) * DD];
__device__ __align__(16) float g_k6[BHN * (N0 / 64) * DD];
__device__ __align__(16) float g_v6[BHN * (N0 / 64) * DD];
__device__ __align__(16) float g_Y678[BHN * (N0 / 64) * DD];
__device__ __align__(16) float g_A678[BHN * (N0 / 64)];

__device__ __forceinline__ float4 f4_scale(float4 a, float s) {
    return make_float4(a.x * s, a.y * s, a.z * s, a.w * s);
}

// ---------------------------------------------------------------------------
// Tri-level kernel, 512 threads. Chunk of 128 tokens at this kernel's finest
// sub-level. Computes 3 consecutive levels, writes combined Y (=y0+y1+y2 at
// finest resolution) + combined A, and (optionally) pools to the next
// tri-level. FLIP0: does sub-level 0 use the sibling block?
//
// Warp roles (14 attention blocks total):
//   w 0-7 : level-0 block w          (sibling = w^1 if FLIP0 else w)
//   w 8-11: level-1 block w-8        (sibling flip)
//   w12-13: level-2 block w-12       (sibling flip)
//   w14-15: pool to next tri-level (global write), if POOL
// ---------------------------------------------------------------------------
template <bool FLIP0, bool POOL>
__global__ __launch_bounds__(512, 1)
void hatt_tri(const float* __restrict__ Q, const float* __restrict__ K,
              const float* __restrict__ V, int ntok, float qscale,
              float* __restrict__ Yout, float* __restrict__ Aout,
              float* __restrict__ Qp, float* __restrict__ Kp,
              float* __restrict__ Vp)
{
    extern __shared__ float sm[];
    float* s_q0 = sm;                    // 128*SD
    float* s_k0 = s_q0 + 128 * SD;       // 128*SD
    float* s_v0 = s_k0 + 128 * SD;       // 128*SD
    float* s_q1 = s_v0 + 128 * SD;       // 64*SD
    float* s_k1 = s_q1 + 64 * SD;
    float* s_v1 = s_k1 + 64 * SD;
    float* s_q2 = s_v1 + 64 * SD;        // 32*SD
    float* s_k2 = s_q2 + 32 * SD;
    float* s_v2 = s_k2 + 32 * SD;
    float* s_y1 = s_v2 + 32 * SD;        // 64*SD
    float* s_y2 = s_y1 + 64 * SD;        // 32*SD
    float* s_a1 = s_y2 + 32 * SD;        // 64
    float* s_a2 = s_a1 + 64;             // 32

    const int tid = threadIdx.x;
    const int bh = blockIdx.y;
    const int c = blockIdx.x;
    const size_t base = ((size_t)bh * (size_t)ntok + (size_t)c * 128) * DD;
    const u64 HALF2 = pk2(0.5f, 0.5f);
    const u64 QTR2  = pk2(0.25f, 0.25f);

    // ---- Phase 1: load chunk (q scaled); batch 12 LDG.128 for MLP ----
    {
        const float4* qg = (const float4*)(Q + base);
        const float4* kg = (const float4*)(K + base);
        const float4* vg = (const float4*)(V + base);
        float4 rq[4], rk[4], rv[4];
#pragma unroll
        for (int it = 0; it < 4; it++) {
            int idx = tid + it * 512;
            rq[it] = qg[idx]; rk[it] = kg[idx]; rv[it] = vg[idx];
        }
#pragma unroll
        for (int it = 0; it < 4; it++) {
            int idx = tid + it * 512;
            int row = idx >> 4, c4 = (idx & 15) << 2;
            *(float4*)(s_q0 + row * SD + c4) = f4_scale(rq[it], qscale);
            *(float4*)(s_k0 + row * SD + c4) = rk[it];
            *(float4*)(s_v0 + row * SD + c4) = rv[it];
        }
    }
    __syncthreads();

    // ---- Phase 2: pool lvl1 (pairs) and lvl2 (quads) from lvl0 ----
    for (int idx = tid; idx < 1536; idx += 512) {
        if (idx < 1024) {
            int t = idx >> 4, c4 = (idx & 15) << 2;
            int r0 = (2 * t) * SD + c4, r1 = (2 * t + 1) * SD + c4, rd = t * SD + c4;
            ulonglong2 a0 = *(const ulonglong2*)(s_q0 + r0);
            ulonglong2 a1 = *(const ulonglong2*)(s_q0 + r1);
            ulonglong2 b0 = *(const ulonglong2*)(s_k0 + r0);
            ulonglong2 b1 = *(const ulonglong2*)(s_k0 + r1);
            ulonglong2 c0 = *(const ulonglong2*)(s_v0 + r0);
            ulonglong2 c1 = *(const ulonglong2*)(s_v0 + r1);
            *(ulonglong2*)(s_q1 + rd) = make_ulonglong2(
                mul2(add2(a0.x, a1.x), HALF2), mul2(add2(a0.y, a1.y), HALF2));
            *(ulonglong2*)(s_k1 + rd) = make_ulonglong2(
                mul2(add2(b0.x, b1.x), HALF2), mul2(add2(b0.y, b1.y), HALF2));
            *(ulonglong2*)(s_v1 + rd) = make_ulonglong2(
                add2(c0.x, c1.x), add2(c0.y, c1.y));
        } else {
            int j = idx - 1024;
            int t = j >> 4, c4 = (j & 15) << 2;
            int rd = t * SD + c4;
            u64 qsx = 0, qsy = 0, ksx = 0, ksy = 0, vsx = 0, vsy = 0;
            // init with first element to avoid add with packed-zero bit tricks
            {
                int r = (4 * t) * SD + c4;
                ulonglong2 a = *(const ulonglong2*)(s_q0 + r);
                ulonglong2 b = *(const ulonglong2*)(s_k0 + r);
                ulonglong2 cc2 = *(const ulonglong2*)(s_v0 + r);
                qsx = a.x; qsy = a.y; ksx = b.x; ksy = b.y; vsx = cc2.x; vsy = cc2.y;
            }
#pragma unroll
            for (int p = 1; p < 4; p++) {
                int r = (4 * t + p) * SD + c4;
                ulonglong2 a = *(const ulonglong2*)(s_q0 + r);
                ulonglong2 b = *(const ulonglong2*)(s_k0 + r);
                ulonglong2 cc2 = *(const ulonglong2*)(s_v0 + r);
                qsx = add2(qsx, a.x); qsy = add2(qsy, a.y);
                ksx = add2(ksx, b.x); ksy = add2(ksy, b.y);
                vsx = add2(vsx, cc2.x); vsy = add2(vsy, cc2.y);
            }
            *(ulonglong2*)(s_q2 + rd) = make_ulonglong2(mul2(qsx, QTR2), mul2(qsy, QTR2));
            *(ulonglong2*)(s_k2 + rd) = make_ulonglong2(mul2(ksx, QTR2), mul2(ksy, QTR2));
            *(ulonglong2*)(s_v2 + rd) = make_ulonglong2(vsx, vsy);
        }
    }
    __syncthreads();

    const int w = tid >> 5;
    const int lane = tid & 31;
    const int i = lane & 15;
    const int dg = lane >> 4;

    // ---- Role pointers ----
    const float* qB = nullptr;
    const float* kB = nullptr;
    const float* vB = nullptr;
    float* yB = nullptr;     // smem y target (lvl1/lvl2 only)
    float* aB = nullptr;
    if (w < 8) {
        int sb = FLIP0 ? (w ^ 1) : w;
        qB = s_q0 + w * 16 * SD;
        kB = s_k0 + sb * 16 * SD;
        vB = s_v0 + sb * 16 * SD;
    } else if (w < 12) {
        int qb = w - 8, sb = qb ^ 1;
        qB = s_q1 + qb * 16 * SD;
        kB = s_k1 + sb * 16 * SD;
        vB = s_v1 + sb * 16 * SD;
        yB = s_y1 + qb * 16 * SD;
        aB = s_a1 + qb * 16;
    } else if (w < 14) {
        int qb = w - 12, sb = qb ^ 1;
        qB = s_q2 + qb * 16 * SD;
        kB = s_k2 + sb * 16 * SD;
        vB = s_v2 + sb * 16 * SD;
        yB = s_y2 + qb * 16 * SD;
        aB = s_a2 + qb * 16;
    }

    // ---- Phase A: S + softmax for all 14 blocks (w14/15: pool) ----
    float Af0[8], Af1[8];   // full 16-wide A row (cols 0-7 / 8-15)
    float rs = 0.f;
    if (w < 14) {
        const float* qr = qB + i * SD;
        const float* kr = kB + dg * 8 * SD;
        u64 acc[8];
#pragma unroll
        for (int jj = 0; jj < 8; jj++) acc[jj] = 0ull;  // packed (0,0)
#pragma unroll
        for (int c4 = 0; c4 < 16; c4++) {
            ulonglong2 qv = *(const ulonglong2*)(qr + c4 * 4);
#pragma unroll
            for (int jj = 0; jj < 8; jj++) {
                ulonglong2 kv = *(const ulonglong2*)(kr + jj * SD + c4 * 4);
                acc[jj] = fma2(qv.x, kv.x, acc[jj]);
                acc[jj] = fma2(qv.y, kv.y, acc[jj]);
            }
        }
        float s[8];
#pragma unroll
        for (int jj = 0; jj < 8; jj++) {
            float lo, hi; up2(acc[jj], lo, hi);
            s[jj] = lo + hi;
        }
        float m = s[0];
#pragma unroll
        for (int jj = 1; jj < 8; jj++) m = fmaxf(m, s[jj]);
        m = fmaxf(m, __shfl_xor_sync(0xffffffffu, m, 16));
        float A[8];
#pragma unroll
        for (int jj = 0; jj < 8; jj++) { A[jj] = __expf(s[jj] - m); rs += A[jj]; }
        rs += __shfl_xor_sync(0xffffffffu, rs, 16);  // full row sum, both halves
#pragma unroll
        for (int jj = 0; jj < 8; jj++) {
            float o = __shfl_xor_sync(0xffffffffu, A[jj], 16);
            Af0[jj] = dg ? o : A[jj];
            Af1[jj] = dg ? A[jj] : o;
        }
    } else if (POOL) {
        int t2 = tid - 448;  // 0..63
        for (int idx = t2; idx < 256; idx += 64) {
            int t = idx >> 4, c4 = (idx & 15) << 2;
            int r0 = (2 * t) * SD + c4, r1 = (2 * t + 1) * SD + c4;
            size_t gi = ((size_t)bh * (size_t)(ntok >> 3) + (size_t)(c * 16 + t)) * DD + c4;
            ulonglong2 a0 = *(const ulonglong2*)(s_q2 + r0);
            ulonglong2 a1 = *(const ulonglong2*)(s_q2 + r1);
            ulonglong2 b0 = *(const ulonglong2*)(s_k2 + r0);
            ulonglong2 b1 = *(const ulonglong2*)(s_k2 + r1);
            ulonglong2 c0 = *(const ulonglong2*)(s_v2 + r0);
            ulonglong2 c1 = *(const ulonglong2*)(s_v2 + r1);
            *(ulonglong2*)(Qp + gi) = make_ulonglong2(
                mul2(add2(a0.x, a1.x), HALF2), mul2(add2(a0.y, a1.y), HALF2));
            *(ulonglong2*)(Kp + gi) = make_ulonglong2(
                mul2(add2(b0.x, b1.x), HALF2), mul2(add2(b0.y, b1.y), HALF2));
            *(ulonglong2*)(Vp + gi) = make_ulonglong2(
                add2(c0.x, c1.x), add2(c0.y, c1.y));
        }
    }
    __syncthreads();

    // ---- Phase B: packed d-split y for all 14 blocks.
    //      Lane covers dims [dg*32, dg*32+32) of its block's row i,
    //      held as 16 packed f32x2 accumulators.
    u64 yp[16];
    if (w < 14) {
#pragma unroll
        for (int cc = 0; cc < 16; cc++) yp[cc] = 0ull;
#pragma unroll
        for (int jj = 0; jj < 8; jj++) {
            u64 a0 = pk2(Af0[jj], Af0[jj]);
            u64 a1 = pk2(Af1[jj], Af1[jj]);
            const ulonglong2* vr0 = (const ulonglong2*)(vB + jj * SD + (dg << 5));
            const ulonglong2* vr1 = (const ulonglong2*)(vB + (8 + jj) * SD + (dg << 5));
#pragma unroll
            for (int cc = 0; cc < 8; cc++) {
                ulonglong2 v0 = vr0[cc];
                ulonglong2 v1 = vr1[cc];
                yp[2 * cc]     = fma2(a0, v0.x, yp[2 * cc]);
                yp[2 * cc + 1] = fma2(a0, v0.y, yp[2 * cc + 1]);
                yp[2 * cc]     = fma2(a1, v1.x, yp[2 * cc]);
                yp[2 * cc + 1] = fma2(a1, v1.y, yp[2 * cc + 1]);
            }
        }
        if (w >= 8) {   // lvl1/lvl2: stage into smem
            float* yo = yB + i * SD + (dg << 5);
#pragma unroll
            for (int cc = 0; cc < 8; cc++)
                *(ulonglong2*)(yo + cc * 4) = make_ulonglong2(yp[2 * cc], yp[2 * cc + 1]);
            if (dg == 0) aB[i] = rs;
        }
    }
    __syncthreads();

    // ---- Phase C (w 0-7): combine with y1/y2, direct global write ----
    if (w < 8) {
        const int r = (w << 4) + i;
        const float* y1r = s_y1 + (r >> 1) * SD + (dg << 5);
        const float* y2r = s_y2 + (r >> 2) * SD + (dg << 5);
        float* yg = Yout + base + r * DD + (dg << 5);
#pragma unroll
        for (int cc = 0; cc < 8; cc++) {
            ulonglong2 u = *(const ulonglong2*)(y1r + cc * 4);
            ulonglong2 t2 = *(const ulonglong2*)(y2r + cc * 4);
            u64 ox = add2(yp[2 * cc], add2(u.x, t2.x));
            u64 oy = add2(yp[2 * cc + 1], add2(u.y, t2.y));
            *(ulonglong2*)(yg + cc * 4) = make_ulonglong2(ox, oy);
        }
        if (dg == 0)
            Aout[(size_t)bh * (size_t)ntok + (size_t)c * 128 + r]
                = rs + s_a1[r >> 1] + s_a2[r >> 2];
    }
}

// ---------------------------------------------------------------------------
// Final combine: out[i] = (Y012[i] + Y345[i>>3] + Y678[i>>6]) / (sumA + eps)
// ---------------------------------------------------------------------------
__global__ __launch_bounds__(256)
void hatt_combine(float* __restrict__ out)
{
    unsigned idx = blockIdx.x * 256u + threadIdx.x;  // < 4194304 float4s
    unsigned f = idx & 15u;
    unsigned tok = (idx >> 4) & 8191u;
    unsigned bh = idx >> 17;

    float4 y = ((const float4*)g_Y012)[idx];
    float4 y3 = ((const float4*)g_Y345)[(((size_t)bh << 10) + (tok >> 3)) * 16 + f];
    float4 y6 = ((const float4*)g_Y678)[(((size_t)bh << 7) + (tok >> 6)) * 16 + f];
    float a = g_A012[((size_t)bh << 13) + tok]
            + g_A345[((size_t)bh << 10) + (tok >> 3)]
            + g_A678[((size_t)bh << 7) + (tok >> 6)] + 1e-8f;
    float inv = 1.0f / a;
    float4 o;
    o.x = (y.x + y3.x + y6.x) * inv;
    o.y = (y.y + y3.y + y6.y) * inv;
    o.z = (y.z + y3.z + y6.z) * inv;
    o.w = (y.w + y3.w + y6.w) * inv;
    ((float4*)out)[idx] = o;
}

// ---------------------------------------------------------------------------
extern "C" void kernel_launch(void* const* d_in, const int* in_sizes, int n_in,
                              void* d_out, int out_size)
{
    const float* q = (const float*)d_in[0];
    const float* k = (const float*)d_in[1];
    const float* v = (const float*)d_in[2];
    float* out = (float*)d_out;
    (void)in_sizes; (void)n_in; (void)out_size;

    void *Y012, *A012, *q3, *k3, *v3, *Y345, *A345, *q6, *k6, *v6, *Y678, *A678;
    cudaGetSymbolAddress(&Y012, g_Y012);
    cudaGetSymbolAddress(&A012, g_A012);
    cudaGetSymbolAddress(&q3, g_q3);
    cudaGetSymbolAddress(&k3, g_k3);
    cudaGetSymbolAddress(&v3, g_v3);
    cudaGetSymbolAddress(&Y345, g_Y345);
    cudaGetSymbolAddress(&A345, g_A345);
    cudaGetSymbolAddress(&q6, g_q6);
    cudaGetSymbolAddress(&k6, g_k6);
    cudaGetSymbolAddress(&v6, g_v6);
    cudaGetSymbolAddress(&Y678, g_Y678);
    cudaGetSymbolAddress(&A678, g_A678);

    const int smem = 52448 * (int)sizeof(float);  // 209792 bytes
    cudaFuncSetAttribute(hatt_tri<false, true>, cudaFuncAttributeMaxDynamicSharedMemorySize, smem);
    cudaFuncSetAttribute(hatt_tri<true, true>, cudaFuncAttributeMaxDynamicSharedMemorySize, smem);
    cudaFuncSetAttribute(hatt_tri<true, false>, cudaFuncAttributeMaxDynamicSharedMemorySize, smem);

    // Levels 0-2 on original tokens (level 0 = self-attention, no flip).
    hatt_tri<false, true><<<dim3(64, 32), 512, smem>>>(
        q, k, v, N0, 0.125f,
        (float*)Y012, (float*)A012, (float*)q3, (float*)k3, (float*)v3);

    // Levels 3-5 on pooled lvl3 (all sibling-flipped).
    hatt_tri<true, true><<<dim3(8, 32), 512, smem>>>(
        (const float*)q3, (const float*)k3, (const float*)v3, N0 / 8, 1.0f,
        (float*)Y345, (float*)A345, (float*)q6, (float*)k6, (float*)v6);

    // Levels 6-8 on pooled lvl6 (all sibling-flipped, no further pooling).
    hatt_tri<true, false><<<dim3(1, 32), 512, smem>>>(
        (const float*)q6, (const float*)k6, (const float*)v6, N0 / 64, 1.0f,
        (float*)Y678, (float*)A678, nullptr, nullptr, nullptr);

    // Final combine + divide.
    hatt_combine<<<4194304 / 256, 256>>>(out);
}

// round 8
// speedup vs baseline: 1.5726x; 1.2161x over previous
#include <cuda_runtime.h>

// ---------------------------------------------------------------------------
// HAttention1D: b=4 h=8 n=8192 d=64, block=16, 9 levels (0..8).
// R7: R6 bi-level grouping with the smem_tri size bug fixed (the tri tail
//     kernel uses FOUR 32-row regions; R6's formula counted three -> OOB).
//     G0: lvl 0-1 (+pool lvl2), G1: lvl 2-3 (+pool lvl4), G2: lvl 4-5
//     (+pool lvl6), G3: tri kernel lvl 6-8, G4: combine.
// ---------------------------------------------------------------------------

#define BHN 32
#define N0  8192
#define DD  64
#define SD  68   // padded smem row stride in floats

typedef unsigned long long u64;

// ---- packed f32x2 helpers ----
__device__ __forceinline__ u64 pk2(float a, float b) {
    u64 r; asm("mov.b64 %0, {%1, %2};" : "=l"(r) : "f"(a), "f"(b)); return r;
}
__device__ __forceinline__ void up2(u64 v, float& a, float& b) {
    asm("mov.b64 {%0, %1}, %2;" : "=f"(a), "=f"(b) : "l"(v));
}
__device__ __forceinline__ u64 fma2(u64 a, u64 b, u64 c) {
    u64 r; asm("fma.rn.f32x2 %0, %1, %2, %3;" : "=l"(r) : "l"(a), "l"(b), "l"(c)); return r;
}
__device__ __forceinline__ u64 add2(u64 a, u64 b) {
    u64 r; asm("add.rn.f32x2 %0, %1, %2;" : "=l"(r) : "l"(a), "l"(b)); return r;
}
__device__ __forceinline__ u64 mul2(u64 a, u64 b) {
    u64 r; asm("mul.rn.f32x2 %0, %1, %2;" : "=l"(r) : "l"(a), "l"(b)); return r;
}

// ---- scratch (device globals; no allocations allowed) ----
__device__ __align__(16) float g_Y01[(size_t)BHN * N0 * DD];          // 64 MB
__device__ __align__(16) float g_A01[BHN * N0];
__device__ __align__(16) float g_q2[BHN * (N0 / 4) * DD];             // 16 MB ea
__device__ __align__(16) float g_k2[BHN * (N0 / 4) * DD];
__device__ __align__(16) float g_v2[BHN * (N0 / 4) * DD];
__device__ __align__(16) float g_Y23[BHN * (N0 / 4) * DD];
__device__ __align__(16) float g_A23[BHN * (N0 / 4)];
__device__ __align__(16) float g_q4[BHN * (N0 / 16) * DD];            // 4 MB ea
__device__ __align__(16) float g_k4[BHN * (N0 / 16) * DD];
__device__ __align__(16) float g_v4[BHN * (N0 / 16) * DD];
__device__ __align__(16) float g_Y45[BHN * (N0 / 16) * DD];
__device__ __align__(16) float g_A45[BHN * (N0 / 16)];
__device__ __align__(16) float g_q6[BHN * (N0 / 64) * DD];            // 1 MB ea
__device__ __align__(16) float g_k6[BHN * (N0 / 64) * DD];
__device__ __align__(16) float g_v6[BHN * (N0 / 64) * DD];
__device__ __align__(16) float g_Y678[BHN * (N0 / 64) * DD];
__device__ __align__(16) float g_A678[BHN * (N0 / 64)];

__device__ __forceinline__ float4 f4_scale(float4 a, float s) {
    return make_float4(a.x * s, a.y * s, a.z * s, a.w * s);
}

// ===========================================================================
// Bi-level kernel: 256 threads, 2 CTAs/SM. Chunk = 64 tokens at the group's
// fine level. Computes 2 levels (sub0: 4 blocks, sub1: 2 blocks), writes
// combined Y (=y0+y1 at fine resolution) + combined A, and pools x4 to the
// next group's level. FLIP0: does sub0 use the sibling block?
//   w 0-3: sub0 block w   w 4-5: sub1 block w-4   w 6-7: pool out
// ===========================================================================
template <bool FLIP0>
__global__ void __launch_bounds__(256, 2)
hatt_bi(const float* __restrict__ Q, const float* __restrict__ K,
        const float* __restrict__ V, int ntok, float qscale,
        float* __restrict__ Yout, float* __restrict__ Aout,
        float* __restrict__ Qp, float* __restrict__ Kp,
        float* __restrict__ Vp)
{
    extern __shared__ float sm[];
    float* s_q0 = sm;                    // 64*SD
    float* s_k0 = s_q0 + 64 * SD;
    float* s_v0 = s_k0 + 64 * SD;
    float* s_q1 = s_v0 + 64 * SD;        // 32*SD
    float* s_k1 = s_q1 + 32 * SD;
    float* s_v1 = s_k1 + 32 * SD;
    float* s_y1 = s_v1 + 32 * SD;        // 32*SD
    float* s_a1 = s_y1 + 32 * SD;        // 32

    const int tid = threadIdx.x;
    const int bh = blockIdx.y;
    const int c = blockIdx.x;
    const size_t base = ((size_t)bh * (size_t)ntok + (size_t)c * 64) * DD;
    const u64 HALF2 = pk2(0.5f, 0.5f);

    // ---- Phase 1: load chunk (q scaled); batched LDG.128 for MLP ----
    {
        const float4* qg = (const float4*)(Q + base);
        const float4* kg = (const float4*)(K + base);
        const float4* vg = (const float4*)(V + base);
        float4 rq[4], rk[4], rv[4];
#pragma unroll
        for (int it = 0; it < 4; it++) {
            int idx = tid + it * 256;
            rq[it] = qg[idx]; rk[it] = kg[idx]; rv[it] = vg[idx];
        }
#pragma unroll
        for (int it = 0; it < 4; it++) {
            int idx = tid + it * 256;
            int row = idx >> 4, c4 = (idx & 15) << 2;
            *(float4*)(s_q0 + row * SD + c4) = f4_scale(rq[it], qscale);
            *(float4*)(s_k0 + row * SD + c4) = rk[it];
            *(float4*)(s_v0 + row * SD + c4) = rv[it];
        }
    }
    __syncthreads();

    // ---- Phase 2: pool to sub-level 1 (32 tokens) ----
    for (int idx = tid; idx < 512; idx += 256) {
        int t = idx >> 4, c4 = (idx & 15) << 2;
        int r0 = (2 * t) * SD + c4, r1 = (2 * t + 1) * SD + c4, rd = t * SD + c4;
        ulonglong2 a0 = *(const ulonglong2*)(s_q0 + r0);
        ulonglong2 a1 = *(const ulonglong2*)(s_q0 + r1);
        ulonglong2 b0 = *(const ulonglong2*)(s_k0 + r0);
        ulonglong2 b1 = *(const ulonglong2*)(s_k0 + r1);
        ulonglong2 c0 = *(const ulonglong2*)(s_v0 + r0);
        ulonglong2 c1 = *(const ulonglong2*)(s_v0 + r1);
        *(ulonglong2*)(s_q1 + rd) = make_ulonglong2(
            mul2(add2(a0.x, a1.x), HALF2), mul2(add2(a0.y, a1.y), HALF2));
        *(ulonglong2*)(s_k1 + rd) = make_ulonglong2(
            mul2(add2(b0.x, b1.x), HALF2), mul2(add2(b0.y, b1.y), HALF2));
        *(ulonglong2*)(s_v1 + rd) = make_ulonglong2(
            add2(c0.x, c1.x), add2(c0.y, c1.y));
    }
    __syncthreads();

    const int w = tid >> 5;
    const int lane = tid & 31;
    const int i = lane & 15;
    const int dg = lane >> 4;

    // ---- Role pointers ----
    const float* qB = nullptr;
    const float* kB = nullptr;
    const float* vB = nullptr;
    if (w < 4) {
        int sb = FLIP0 ? (w ^ 1) : w;
        qB = s_q0 + w * 16 * SD;
        kB = s_k0 + sb * 16 * SD;
        vB = s_v0 + sb * 16 * SD;
    } else if (w < 6) {
        int qb = w - 4, sb = qb ^ 1;
        qB = s_q1 + qb * 16 * SD;
        kB = s_k1 + sb * 16 * SD;
        vB = s_v1 + sb * 16 * SD;
    }

    // ---- Phase A: S + softmax for 6 blocks; warps 6-7 pool out ----
    float Af0[8], Af1[8];
    float rs = 0.f;
    if (w < 6) {
        const float* qr = qB + i * SD;
        const float* kr = kB + dg * 8 * SD;
        u64 acc[8];
#pragma unroll
        for (int jj = 0; jj < 8; jj++) acc[jj] = 0ull;
#pragma unroll
        for (int c4 = 0; c4 < 16; c4++) {
            ulonglong2 qv = *(const ulonglong2*)(qr + c4 * 4);
#pragma unroll
            for (int jj = 0; jj < 8; jj++) {
                ulonglong2 kv = *(const ulonglong2*)(kr + jj * SD + c4 * 4);
                acc[jj] = fma2(qv.x, kv.x, acc[jj]);
                acc[jj] = fma2(qv.y, kv.y, acc[jj]);
            }
        }
        float s[8];
#pragma unroll
        for (int jj = 0; jj < 8; jj++) {
            float lo, hi; up2(acc[jj], lo, hi);
            s[jj] = lo + hi;
        }
        float m = s[0];
#pragma unroll
        for (int jj = 1; jj < 8; jj++) m = fmaxf(m, s[jj]);
        m = fmaxf(m, __shfl_xor_sync(0xffffffffu, m, 16));
        float A[8];
#pragma unroll
        for (int jj = 0; jj < 8; jj++) { A[jj] = __expf(s[jj] - m); rs += A[jj]; }
        rs += __shfl_xor_sync(0xffffffffu, rs, 16);
#pragma unroll
        for (int jj = 0; jj < 8; jj++) {
            float o = __shfl_xor_sync(0xffffffffu, A[jj], 16);
            Af0[jj] = dg ? o : A[jj];
            Af1[jj] = dg ? A[jj] : o;
        }
    } else {
        // pool x2 from sub-level 1 -> next group's fine level (global write)
        int t2 = tid - 192;  // 0..63
        for (int idx = t2; idx < 256; idx += 64) {
            int t = idx >> 4, c4 = (idx & 15) << 2;
            int r0 = (2 * t) * SD + c4, r1 = (2 * t + 1) * SD + c4;
            size_t gi = ((size_t)bh * (size_t)(ntok >> 2) + (size_t)(c * 16 + t)) * DD + c4;
            ulonglong2 a0 = *(const ulonglong2*)(s_q1 + r0);
            ulonglong2 a1 = *(const ulonglong2*)(s_q1 + r1);
            ulonglong2 b0 = *(const ulonglong2*)(s_k1 + r0);
            ulonglong2 b1 = *(const ulonglong2*)(s_k1 + r1);
            ulonglong2 c0 = *(const ulonglong2*)(s_v1 + r0);
            ulonglong2 c1 = *(const ulonglong2*)(s_v1 + r1);
            *(ulonglong2*)(Qp + gi) = make_ulonglong2(
                mul2(add2(a0.x, a1.x), HALF2), mul2(add2(a0.y, a1.y), HALF2));
            *(ulonglong2*)(Kp + gi) = make_ulonglong2(
                mul2(add2(b0.x, b1.x), HALF2), mul2(add2(b0.y, b1.y), HALF2));
            *(ulonglong2*)(Vp + gi) = make_ulonglong2(
                add2(c0.x, c1.x), add2(c0.y, c1.y));
        }
    }
    __syncthreads();

    // ---- Phase B: packed d-split y for 6 blocks ----
    u64 yp[16];
    if (w < 6) {
#pragma unroll
        for (int cc = 0; cc < 16; cc++) yp[cc] = 0ull;
#pragma unroll
        for (int jj = 0; jj < 8; jj++) {
            u64 a0 = pk2(Af0[jj], Af0[jj]);
            u64 a1 = pk2(Af1[jj], Af1[jj]);
            const ulonglong2* vr0 = (const ulonglong2*)(vB + jj * SD + (dg << 5));
            const ulonglong2* vr1 = (const ulonglong2*)(vB + (8 + jj) * SD + (dg << 5));
#pragma unroll
            for (int cc = 0; cc < 8; cc++) {
                ulonglong2 v0 = vr0[cc];
                ulonglong2 v1 = vr1[cc];
                yp[2 * cc]     = fma2(a0, v0.x, yp[2 * cc]);
                yp[2 * cc + 1] = fma2(a0, v0.y, yp[2 * cc + 1]);
                yp[2 * cc]     = fma2(a1, v1.x, yp[2 * cc]);
                yp[2 * cc + 1] = fma2(a1, v1.y, yp[2 * cc + 1]);
            }
        }
        if (w >= 4) {   // sub1: stage into smem
            float* yo = s_y1 + ((w - 4) * 16 + i) * SD + (dg << 5);
#pragma unroll
            for (int cc = 0; cc < 8; cc++)
                *(ulonglong2*)(yo + cc * 4) = make_ulonglong2(yp[2 * cc], yp[2 * cc + 1]);
            if (dg == 0) s_a1[(w - 4) * 16 + i] = rs;
        }
    }
    __syncthreads();

    // ---- Phase C (w 0-3): combine with y1, direct global write ----
    if (w < 4) {
        const int r = (w << 4) + i;
        const float* y1r = s_y1 + (r >> 1) * SD + (dg << 5);
        float* yg = Yout + base + r * DD + (dg << 5);
#pragma unroll
        for (int cc = 0; cc < 8; cc++) {
            ulonglong2 u = *(const ulonglong2*)(y1r + cc * 4);
            u64 ox = add2(yp[2 * cc], u.x);
            u64 oy = add2(yp[2 * cc + 1], u.y);
            *(ulonglong2*)(yg + cc * 4) = make_ulonglong2(ox, oy);
        }
        if (dg == 0)
            Aout[(size_t)bh * (size_t)ntok + (size_t)c * 64 + r] = rs + s_a1[r >> 1];
    }
}

// ===========================================================================
// Tri-level tail kernel (levels 6-8, n=128 -> one chunk per bh, 32 CTAs).
// 512 threads, sibling flip at every sub-level, no pooling.
// smem: 128*SD*3 + 64*SD*4 + 32*SD*4 + 96 floats  (FOUR 32-row regions!)
// ===========================================================================
__global__ __launch_bounds__(512, 1)
void hatt_tri(const float* __restrict__ Q, const float* __restrict__ K,
              const float* __restrict__ V, int ntok,
              float* __restrict__ Yout, float* __restrict__ Aout)
{
    extern __shared__ float sm[];
    float* s_q0 = sm;                    // 128*SD
    float* s_k0 = s_q0 + 128 * SD;
    float* s_v0 = s_k0 + 128 * SD;
    float* s_q1 = s_v0 + 128 * SD;       // 64*SD
    float* s_k1 = s_q1 + 64 * SD;
    float* s_v1 = s_k1 + 64 * SD;
    float* s_q2 = s_v1 + 64 * SD;        // 32*SD
    float* s_k2 = s_q2 + 32 * SD;
    float* s_v2 = s_k2 + 32 * SD;
    float* s_y1 = s_v2 + 32 * SD;        // 64*SD
    float* s_y2 = s_y1 + 64 * SD;        // 32*SD
    float* s_a1 = s_y2 + 32 * SD;        // 64
    float* s_a2 = s_a1 + 64;             // 32

    const int tid = threadIdx.x;
    const int bh = blockIdx.y;
    const size_t base = (size_t)bh * (size_t)ntok * DD;
    const u64 HALF2 = pk2(0.5f, 0.5f);
    const u64 QTR2  = pk2(0.25f, 0.25f);

    {
        const float4* qg = (const float4*)(Q + base);
        const float4* kg = (const float4*)(K + base);
        const float4* vg = (const float4*)(V + base);
        for (int idx = tid; idx < 2048; idx += 512) {
            int row = idx >> 4, c4 = (idx & 15) << 2;
            *(float4*)(s_q0 + row * SD + c4) = qg[idx];
            *(float4*)(s_k0 + row * SD + c4) = kg[idx];
            *(float4*)(s_v0 + row * SD + c4) = vg[idx];
        }
    }
    __syncthreads();

    for (int idx = tid; idx < 1536; idx += 512) {
        if (idx < 1024) {
            int t = idx >> 4, c4 = (idx & 15) << 2;
            int r0 = (2 * t) * SD + c4, r1 = (2 * t + 1) * SD + c4, rd = t * SD + c4;
            ulonglong2 a0 = *(const ulonglong2*)(s_q0 + r0);
            ulonglong2 a1 = *(const ulonglong2*)(s_q0 + r1);
            ulonglong2 b0 = *(const ulonglong2*)(s_k0 + r0);
            ulonglong2 b1 = *(const ulonglong2*)(s_k0 + r1);
            ulonglong2 c0 = *(const ulonglong2*)(s_v0 + r0);
            ulonglong2 c1 = *(const ulonglong2*)(s_v0 + r1);
            *(ulonglong2*)(s_q1 + rd) = make_ulonglong2(
                mul2(add2(a0.x, a1.x), HALF2), mul2(add2(a0.y, a1.y), HALF2));
            *(ulonglong2*)(s_k1 + rd) = make_ulonglong2(
                mul2(add2(b0.x, b1.x), HALF2), mul2(add2(b0.y, b1.y), HALF2));
            *(ulonglong2*)(s_v1 + rd) = make_ulonglong2(
                add2(c0.x, c1.x), add2(c0.y, c1.y));
        } else {
            int j = idx - 1024;
            int t = j >> 4, c4 = (j & 15) << 2;
            int rd = t * SD + c4;
            u64 qsx, qsy, ksx, ksy, vsx, vsy;
            {
                int r = (4 * t) * SD + c4;
                ulonglong2 a = *(const ulonglong2*)(s_q0 + r);
                ulonglong2 b = *(const ulonglong2*)(s_k0 + r);
                ulonglong2 cc2 = *(const ulonglong2*)(s_v0 + r);
                qsx = a.x; qsy = a.y; ksx = b.x; ksy = b.y; vsx = cc2.x; vsy = cc2.y;
            }
#pragma unroll
            for (int p = 1; p < 4; p++) {
                int r = (4 * t + p) * SD + c4;
                ulonglong2 a = *(const ulonglong2*)(s_q0 + r);
                ulonglong2 b = *(const ulonglong2*)(s_k0 + r);
                ulonglong2 cc2 = *(const ulonglong2*)(s_v0 + r);
                qsx = add2(qsx, a.x); qsy = add2(qsy, a.y);
                ksx = add2(ksx, b.x); ksy = add2(ksy, b.y);
                vsx = add2(vsx, cc2.x); vsy = add2(vsy, cc2.y);
            }
            *(ulonglong2*)(s_q2 + rd) = make_ulonglong2(mul2(qsx, QTR2), mul2(qsy, QTR2));
            *(ulonglong2*)(s_k2 + rd) = make_ulonglong2(mul2(ksx, QTR2), mul2(ksy, QTR2));
            *(ulonglong2*)(s_v2 + rd) = make_ulonglong2(vsx, vsy);
        }
    }
    __syncthreads();

    const int w = tid >> 5;
    const int lane = tid & 31;
    const int i = lane & 15;
    const int dg = lane >> 4;

    const float* qB = nullptr;
    const float* kB = nullptr;
    const float* vB = nullptr;
    float* yB = nullptr;
    float* aB = nullptr;
    if (w < 8) {
        int sb = w ^ 1;
        qB = s_q0 + w * 16 * SD;
        kB = s_k0 + sb * 16 * SD;
        vB = s_v0 + sb * 16 * SD;
    } else if (w < 12) {
        int qb = w - 8, sb = qb ^ 1;
        qB = s_q1 + qb * 16 * SD;
        kB = s_k1 + sb * 16 * SD;
        vB = s_v1 + sb * 16 * SD;
        yB = s_y1 + qb * 16 * SD;
        aB = s_a1 + qb * 16;
    } else if (w < 14) {
        int qb = w - 12, sb = qb ^ 1;
        qB = s_q2 + qb * 16 * SD;
        kB = s_k2 + sb * 16 * SD;
        vB = s_v2 + sb * 16 * SD;
        yB = s_y2 + qb * 16 * SD;
        aB = s_a2 + qb * 16;
    }

    float Af0[8], Af1[8];
    float rs = 0.f;
    if (w < 14) {
        const float* qr = qB + i * SD;
        const float* kr = kB + dg * 8 * SD;
        u64 acc[8];
#pragma unroll
        for (int jj = 0; jj < 8; jj++) acc[jj] = 0ull;
#pragma unroll
        for (int c4 = 0; c4 < 16; c4++) {
            ulonglong2 qv = *(const ulonglong2*)(qr + c4 * 4);
#pragma unroll
            for (int jj = 0; jj < 8; jj++) {
                ulonglong2 kv = *(const ulonglong2*)(kr + jj * SD + c4 * 4);
                acc[jj] = fma2(qv.x, kv.x, acc[jj]);
                acc[jj] = fma2(qv.y, kv.y, acc[jj]);
            }
        }
        float s[8];
#pragma unroll
        for (int jj = 0; jj < 8; jj++) {
            float lo, hi; up2(acc[jj], lo, hi);
            s[jj] = lo + hi;
        }
        float m = s[0];
#pragma unroll
        for (int jj = 1; jj < 8; jj++) m = fmaxf(m, s[jj]);
        m = fmaxf(m, __shfl_xor_sync(0xffffffffu, m, 16));
        float A[8];
#pragma unroll
        for (int jj = 0; jj < 8; jj++) { A[jj] = __expf(s[jj] - m); rs += A[jj]; }
        rs += __shfl_xor_sync(0xffffffffu, rs, 16);
#pragma unroll
        for (int jj = 0; jj < 8; jj++) {
            float o = __shfl_xor_sync(0xffffffffu, A[jj], 16);
            Af0[jj] = dg ? o : A[jj];
            Af1[jj] = dg ? A[jj] : o;
        }
    }
    __syncthreads();

    u64 yp[16];
    if (w < 14) {
#pragma unroll
        for (int cc = 0; cc < 16; cc++) yp[cc] = 0ull;
#pragma unroll
        for (int jj = 0; jj < 8; jj++) {
            u64 a0 = pk2(Af0[jj], Af0[jj]);
            u64 a1 = pk2(Af1[jj], Af1[jj]);
            const ulonglong2* vr0 = (const ulonglong2*)(vB + jj * SD + (dg << 5));
            const ulonglong2* vr1 = (const ulonglong2*)(vB + (8 + jj) * SD + (dg << 5));
#pragma unroll
            for (int cc = 0; cc < 8; cc++) {
                ulonglong2 v0 = vr0[cc];
                ulonglong2 v1 = vr1[cc];
                yp[2 * cc]     = fma2(a0, v0.x, yp[2 * cc]);
                yp[2 * cc + 1] = fma2(a0, v0.y, yp[2 * cc + 1]);
                yp[2 * cc]     = fma2(a1, v1.x, yp[2 * cc]);
                yp[2 * cc + 1] = fma2(a1, v1.y, yp[2 * cc + 1]);
            }
        }
        if (w >= 8) {
            float* yo = yB + i * SD + (dg << 5);
#pragma unroll
            for (int cc = 0; cc < 8; cc++)
                *(ulonglong2*)(yo + cc * 4) = make_ulonglong2(yp[2 * cc], yp[2 * cc + 1]);
            if (dg == 0) aB[i] = rs;
        }
    }
    __syncthreads();

    if (w < 8) {
        const int r = (w << 4) + i;
        const float* y1r = s_y1 + (r >> 1) * SD + (dg << 5);
        const float* y2r = s_y2 + (r >> 2) * SD + (dg << 5);
        float* yg = Yout + base + r * DD + (dg << 5);
#pragma unroll
        for (int cc = 0; cc < 8; cc++) {
            ulonglong2 u = *(const ulonglong2*)(y1r + cc * 4);
            ulonglong2 t2 = *(const ulonglong2*)(y2r + cc * 4);
            u64 ox = add2(yp[2 * cc], add2(u.x, t2.x));
            u64 oy = add2(yp[2 * cc + 1], add2(u.y, t2.y));
            *(ulonglong2*)(yg + cc * 4) = make_ulonglong2(ox, oy);
        }
        if (dg == 0)
            Aout[(size_t)bh * (size_t)ntok + r] = rs + s_a1[r >> 1] + s_a2[r >> 2];
    }
}

// ---------------------------------------------------------------------------
// Final combine:
// out[i] = (Y01[i] + Y23[i>>2] + Y45[i>>4] + Y678[i>>6]) / (sumA + eps)
// ---------------------------------------------------------------------------
__global__ __launch_bounds__(256)
void hatt_combine(float* __restrict__ out)
{
    unsigned idx = blockIdx.x * 256u + threadIdx.x;  // < 4194304 float4s
    unsigned f = idx & 15u;
    unsigned tok = (idx >> 4) & 8191u;
    unsigned bh = idx >> 17;

    float4 y = ((const float4*)g_Y01)[idx];
    float4 y2 = ((const float4*)g_Y23)[(((size_t)bh << 11) + (tok >> 2)) * 16 + f];
    float4 y4 = ((const float4*)g_Y45)[(((size_t)bh << 9) + (tok >> 4)) * 16 + f];
    float4 y6 = ((const float4*)g_Y678)[(((size_t)bh << 7) + (tok >> 6)) * 16 + f];
    float a = g_A01[((size_t)bh << 13) + tok]
            + g_A23[((size_t)bh << 11) + (tok >> 2)]
            + g_A45[((size_t)bh << 9) + (tok >> 4)]
            + g_A678[((size_t)bh << 7) + (tok >> 6)] + 1e-8f;
    float inv = 1.0f / a;
    float4 o;
    o.x = (y.x + y2.x + y4.x + y6.x) * inv;
    o.y = (y.y + y2.y + y4.y + y6.y) * inv;
    o.z = (y.z + y2.z + y4.z + y6.z) * inv;
    o.w = (y.w + y2.w + y4.w + y6.w) * inv;
    ((float4*)out)[idx] = o;
}

// ---------------------------------------------------------------------------
extern "C" void kernel_launch(void* const* d_in, const int* in_sizes, int n_in,
                              void* d_out, int out_size)
{
    const float* q = (const float*)d_in[0];
    const float* k = (const float*)d_in[1];
    const float* v = (const float*)d_in[2];
    float* out = (float*)d_out;
    (void)in_sizes; (void)n_in; (void)out_size;

    void *Y01, *A01, *q2, *k2, *v2, *Y23, *A23, *q4, *k4, *v4, *Y45, *A45;
    void *q6, *k6, *v6, *Y678, *A678;
    cudaGetSymbolAddress(&Y01, g_Y01);
    cudaGetSymbolAddress(&A01, g_A01);
    cudaGetSymbolAddress(&q2, g_q2);
    cudaGetSymbolAddress(&k2, g_k2);
    cudaGetSymbolAddress(&v2, g_v2);
    cudaGetSymbolAddress(&Y23, g_Y23);
    cudaGetSymbolAddress(&A23, g_A23);
    cudaGetSymbolAddress(&q4, g_q4);
    cudaGetSymbolAddress(&k4, g_k4);
    cudaGetSymbolAddress(&v4, g_v4);
    cudaGetSymbolAddress(&Y45, g_Y45);
    cudaGetSymbolAddress(&A45, g_A45);
    cudaGetSymbolAddress(&q6, g_q6);
    cudaGetSymbolAddress(&k6, g_k6);
    cudaGetSymbolAddress(&v6, g_v6);
    cudaGetSymbolAddress(&Y678, g_Y678);
    cudaGetSymbolAddress(&A678, g_A678);

    // bi: 64*SD*3 + 32*SD*4 + 32 = 21792 floats = 87168 B (2 CTAs/SM)
    const int smem_bi = (64 * SD * 3 + 32 * SD * 4 + 32) * (int)sizeof(float);
    // tri: 128*SD*3 + 64*SD*4 + 32*SD*4 + 96 = 52320 floats = 209280 B
    //      (four 32-row regions: q2,k2,v2,y2 — R6 counted three -> OOB)
    const int smem_tri = (128 * SD * 3 + 64 * SD * 4 + 32 * SD * 4 + 96) * (int)sizeof(float);
    cudaFuncSetAttribute(hatt_bi<false>, cudaFuncAttributeMaxDynamicSharedMemorySize, smem_bi);
    cudaFuncSetAttribute(hatt_bi<true>, cudaFuncAttributeMaxDynamicSharedMemorySize, smem_bi);
    cudaFuncSetAttribute(hatt_tri, cudaFuncAttributeMaxDynamicSharedMemorySize, smem_tri);

    // G0: levels 0-1 on original tokens (level 0 = self-attention, no flip).
    hatt_bi<false><<<dim3(128, 32), 256, smem_bi>>>(
        q, k, v, N0, 0.125f,
        (float*)Y01, (float*)A01, (float*)q2, (float*)k2, (float*)v2);

    // G1: levels 2-3 on pooled lvl2.
    hatt_bi<true><<<dim3(32, 32), 256, smem_bi>>>(
        (const float*)q2, (const float*)k2, (const float*)v2, N0 / 4, 1.0f,
        (float*)Y23, (float*)A23, (float*)q4, (float*)k4, (float*)v4);

    // G2: levels 4-5 on pooled lvl4.
    hatt_bi<true><<<dim3(8, 32), 256, smem_bi>>>(
        (const float*)q4, (const float*)k4, (const float*)v4, N0 / 16, 1.0f,
        (float*)Y45, (float*)A45, (float*)q6, (float*)k6, (float*)v6);

    // G3: levels 6-8 on pooled lvl6 (tri tail, 32 CTAs).
    hatt_tri<<<dim3(1, 32), 512, smem_tri>>>(
        (const float*)q6, (const float*)k6, (const float*)v6, N0 / 64,
        (float*)Y678, (float*)A678);

    // G4: final combine + divide.
    hatt_combine<<<4194304 / 256, 256>>>(out);
}

// round 9
// speedup vs baseline: 1.6619x; 1.0567x over previous
#include <cuda_runtime.h>

// ---------------------------------------------------------------------------
// HAttention1D: b=4 h=8 n=8192 d=64, block=16, 9 levels (0..8).
// R8: Phase-1 thread-local pooling (consecutive-row mapping) removes Phase 2
//     + one barrier + the warps-6/7 pool job; s_y1 aliased onto s_q1;
//     tri tail replaced by bi(lvl6) + 64-thread lvl8 micro kernel.
// Groups: G0 lvl0-1 (+pool lvl2), G1 lvl2-3 (+pool lvl4), G2 lvl4-5
//         (+pool lvl6), G3 lvl6-7 (+pool lvl8), G4 lvl8, G5 combine.
// ---------------------------------------------------------------------------

#define BHN 32
#define N0  8192
#define DD  64
#define SD  68   // padded smem row stride in floats

typedef unsigned long long u64;

// ---- packed f32x2 helpers ----
__device__ __forceinline__ u64 pk2(float a, float b) {
    u64 r; asm("mov.b64 %0, {%1, %2};" : "=l"(r) : "f"(a), "f"(b)); return r;
}
__device__ __forceinline__ void up2(u64 v, float& a, float& b) {
    asm("mov.b64 {%0, %1}, %2;" : "=f"(a), "=f"(b) : "l"(v));
}
__device__ __forceinline__ u64 fma2(u64 a, u64 b, u64 c) {
    u64 r; asm("fma.rn.f32x2 %0, %1, %2, %3;" : "=l"(r) : "l"(a), "l"(b), "l"(c)); return r;
}
__device__ __forceinline__ u64 add2(u64 a, u64 b) {
    u64 r; asm("add.rn.f32x2 %0, %1, %2;" : "=l"(r) : "l"(a), "l"(b)); return r;
}

// ---- scratch (device globals; no allocations allowed) ----
__device__ __align__(16) float g_Y01[(size_t)BHN * N0 * DD];          // 64 MB
__device__ __align__(16) float g_A01[BHN * N0];
__device__ __align__(16) float g_q2[BHN * (N0 / 4) * DD];             // 16 MB ea
__device__ __align__(16) float g_k2[BHN * (N0 / 4) * DD];
__device__ __align__(16) float g_v2[BHN * (N0 / 4) * DD];
__device__ __align__(16) float g_Y23[BHN * (N0 / 4) * DD];
__device__ __align__(16) float g_A23[BHN * (N0 / 4)];
__device__ __align__(16) float g_q4[BHN * (N0 / 16) * DD];            // 4 MB ea
__device__ __align__(16) float g_k4[BHN * (N0 / 16) * DD];
__device__ __align__(16) float g_v4[BHN * (N0 / 16) * DD];
__device__ __align__(16) float g_Y45[BHN * (N0 / 16) * DD];
__device__ __align__(16) float g_A45[BHN * (N0 / 16)];
__device__ __align__(16) float g_q6[BHN * (N0 / 64) * DD];            // 1 MB ea
__device__ __align__(16) float g_k6[BHN * (N0 / 64) * DD];
__device__ __align__(16) float g_v6[BHN * (N0 / 64) * DD];
__device__ __align__(16) float g_Y67[BHN * (N0 / 64) * DD];
__device__ __align__(16) float g_A67[BHN * (N0 / 64)];
__device__ __align__(16) float g_q8[BHN * (N0 / 256) * DD];           // 256 KB ea
__device__ __align__(16) float g_k8[BHN * (N0 / 256) * DD];
__device__ __align__(16) float g_v8[BHN * (N0 / 256) * DD];
__device__ __align__(16) float g_Y8[BHN * (N0 / 256) * DD];
__device__ __align__(16) float g_A8[BHN * (N0 / 256)];

__device__ __forceinline__ float4 f4_scale(float4 a, float s) {
    return make_float4(a.x * s, a.y * s, a.z * s, a.w * s);
}
__device__ __forceinline__ float4 f4_add(float4 a, float4 b) {
    return make_float4(a.x + b.x, a.y + b.y, a.z + b.z, a.w + b.w);
}
__device__ __forceinline__ float4 f4_avg(float4 a, float4 b) {
    return make_float4((a.x + b.x) * 0.5f, (a.y + b.y) * 0.5f,
                       (a.z + b.z) * 0.5f, (a.w + b.w) * 0.5f);
}

// ===========================================================================
// Bi-level kernel: 256 threads, 2 CTAs/SM. Chunk = 64 tokens at the group's
// fine level. Phase 1 does ALL pooling thread-locally (fine->smem, lvl1->smem,
// lvl2->global). Warp roles in A/B: w0-3 sub0 block w (sibling w^1 if FLIP0
// else w); w4-5 sub1 block w-4 (sibling flip); w6-7 idle.
// smem: q0,k0,v0 (64*SD) + q1(/y1),k1,v1 (32*SD) + a1(32) = 78464 B.
// ===========================================================================
template <bool FLIP0>
__global__ void __launch_bounds__(256, 2)
hatt_bi(const float* __restrict__ Q, const float* __restrict__ K,
        const float* __restrict__ V, int ntok, float qscale,
        float* __restrict__ Yout, float* __restrict__ Aout,
        float* __restrict__ Qp, float* __restrict__ Kp,
        float* __restrict__ Vp)
{
    extern __shared__ float sm[];
    float* s_q0 = sm;                    // 64*SD
    float* s_k0 = s_q0 + 64 * SD;
    float* s_v0 = s_k0 + 64 * SD;
    float* s_q1 = s_v0 + 64 * SD;        // 32*SD (aliased as s_y1 in Phase B+)
    float* s_k1 = s_q1 + 32 * SD;
    float* s_v1 = s_k1 + 32 * SD;
    float* s_a1 = s_v1 + 32 * SD;        // 32
    float* s_y1 = s_q1;                  // alias: q1 dead after Phase A

    const int tid = threadIdx.x;
    const int bh = blockIdx.y;
    const int c = blockIdx.x;
    const size_t base = ((size_t)bh * (size_t)ntok + (size_t)c * 64) * DD;

    // ---- Phase 1: load 4 consecutive rows/thread, pool lvl1+lvl2 locally ----
    {
        const int u = tid >> 4;          // 0..15 (quad index)
        const int cq = tid & 15;         // float4 column
        const int c4 = cq << 2;          // float column
        const float4* qf = (const float4*)(Q + base);
        const float4* kf = (const float4*)(K + base);
        const float4* vf = (const float4*)(V + base);
        const int i0 = (u << 6) + cq;    // (4u)*16 + cq
        float4 q0 = qf[i0], q1 = qf[i0 + 16], q2 = qf[i0 + 32], q3 = qf[i0 + 48];
        float4 k0 = kf[i0], k1 = kf[i0 + 16], k2 = kf[i0 + 32], k3 = kf[i0 + 48];
        float4 v0 = vf[i0], v1 = vf[i0 + 16], v2 = vf[i0 + 32], v3 = vf[i0 + 48];
        q0 = f4_scale(q0, qscale); q1 = f4_scale(q1, qscale);
        q2 = f4_scale(q2, qscale); q3 = f4_scale(q3, qscale);

        const int r0 = (u << 2) * SD + c4;
        *(float4*)(s_q0 + r0) = q0;           *(float4*)(s_q0 + r0 + SD) = q1;
        *(float4*)(s_q0 + r0 + 2 * SD) = q2;  *(float4*)(s_q0 + r0 + 3 * SD) = q3;
        *(float4*)(s_k0 + r0) = k0;           *(float4*)(s_k0 + r0 + SD) = k1;
        *(float4*)(s_k0 + r0 + 2 * SD) = k2;  *(float4*)(s_k0 + r0 + 3 * SD) = k3;
        *(float4*)(s_v0 + r0) = v0;           *(float4*)(s_v0 + r0 + SD) = v1;
        *(float4*)(s_v0 + r0 + 2 * SD) = v2;  *(float4*)(s_v0 + r0 + 3 * SD) = v3;

        float4 qa = f4_avg(q0, q1), qb = f4_avg(q2, q3);
        float4 ka = f4_avg(k0, k1), kb = f4_avg(k2, k3);
        float4 va = f4_add(v0, v1), vb = f4_add(v2, v3);
        const int r1 = (u << 1) * SD + c4;
        *(float4*)(s_q1 + r1) = qa;  *(float4*)(s_q1 + r1 + SD) = qb;
        *(float4*)(s_k1 + r1) = ka;  *(float4*)(s_k1 + r1 + SD) = kb;
        *(float4*)(s_v1 + r1) = va;  *(float4*)(s_v1 + r1 + SD) = vb;

        // lvl2 pool-out: row u of the chunk's 16 pooled rows; idx = tid.
        const size_t gi4 = ((size_t)bh * (size_t)(ntok >> 2) + (size_t)(c * 16)) * 16 + tid;
        ((float4*)Qp)[gi4] = f4_avg(qa, qb);
        ((float4*)Kp)[gi4] = f4_avg(ka, kb);
        ((float4*)Vp)[gi4] = f4_add(va, vb);
    }
    __syncthreads();

    const int w = tid >> 5;
    const int lane = tid & 31;
    const int i = lane & 15;
    const int dg = lane >> 4;

    // ---- Role pointers ----
    const float* qB = nullptr;
    const float* kB = nullptr;
    const float* vB = nullptr;
    if (w < 4) {
        int sb = FLIP0 ? (w ^ 1) : w;
        qB = s_q0 + w * 16 * SD;
        kB = s_k0 + sb * 16 * SD;
        vB = s_v0 + sb * 16 * SD;
    } else if (w < 6) {
        int qb = w - 4, sb = qb ^ 1;
        qB = s_q1 + qb * 16 * SD;
        kB = s_k1 + sb * 16 * SD;
        vB = s_v1 + sb * 16 * SD;
    }

    // ---- Phase A: S + softmax for 6 blocks ----
    float Af0[8], Af1[8];
    float rs = 0.f;
    if (w < 6) {
        const float* qr = qB + i * SD;
        const float* kr = kB + dg * 8 * SD;
        u64 acc[8];
#pragma unroll
        for (int jj = 0; jj < 8; jj++) acc[jj] = 0ull;
#pragma unroll
        for (int c4 = 0; c4 < 16; c4++) {
            ulonglong2 qv = *(const ulonglong2*)(qr + c4 * 4);
#pragma unroll
            for (int jj = 0; jj < 8; jj++) {
                ulonglong2 kv = *(const ulonglong2*)(kr + jj * SD + c4 * 4);
                acc[jj] = fma2(qv.x, kv.x, acc[jj]);
                acc[jj] = fma2(qv.y, kv.y, acc[jj]);
            }
        }
        float s[8];
#pragma unroll
        for (int jj = 0; jj < 8; jj++) {
            float lo, hi; up2(acc[jj], lo, hi);
            s[jj] = lo + hi;
        }
        float m = s[0];
#pragma unroll
        for (int jj = 1; jj < 8; jj++) m = fmaxf(m, s[jj]);
        m = fmaxf(m, __shfl_xor_sync(0xffffffffu, m, 16));
        float A[8];
#pragma unroll
        for (int jj = 0; jj < 8; jj++) { A[jj] = __expf(s[jj] - m); rs += A[jj]; }
        rs += __shfl_xor_sync(0xffffffffu, rs, 16);
#pragma unroll
        for (int jj = 0; jj < 8; jj++) {
            float o = __shfl_xor_sync(0xffffffffu, A[jj], 16);
            Af0[jj] = dg ? o : A[jj];
            Af1[jj] = dg ? A[jj] : o;
        }
    }
    __syncthreads();

    // ---- Phase B: packed d-split y for 6 blocks ----
    u64 yp[16];
    if (w < 6) {
#pragma unroll
        for (int cc = 0; cc < 16; cc++) yp[cc] = 0ull;
#pragma unroll
        for (int jj = 0; jj < 8; jj++) {
            u64 a0 = pk2(Af0[jj], Af0[jj]);
            u64 a1 = pk2(Af1[jj], Af1[jj]);
            const ulonglong2* vr0 = (const ulonglong2*)(vB + jj * SD + (dg << 5));
            const ulonglong2* vr1 = (const ulonglong2*)(vB + (8 + jj) * SD + (dg << 5));
#pragma unroll
            for (int cc = 0; cc < 8; cc++) {
                ulonglong2 v0 = vr0[cc];
                ulonglong2 v1 = vr1[cc];
                yp[2 * cc]     = fma2(a0, v0.x, yp[2 * cc]);
                yp[2 * cc + 1] = fma2(a0, v0.y, yp[2 * cc + 1]);
                yp[2 * cc]     = fma2(a1, v1.x, yp[2 * cc]);
                yp[2 * cc + 1] = fma2(a1, v1.y, yp[2 * cc + 1]);
            }
        }
        if (w >= 4) {   // sub1: stage into smem (s_y1 aliases dead s_q1)
            float* yo = s_y1 + ((w - 4) * 16 + i) * SD + (dg << 5);
#pragma unroll
            for (int cc = 0; cc < 8; cc++)
                *(ulonglong2*)(yo + cc * 4) = make_ulonglong2(yp[2 * cc], yp[2 * cc + 1]);
            if (dg == 0) s_a1[(w - 4) * 16 + i] = rs;
        }
    }
    __syncthreads();

    // ---- Phase C (w 0-3): combine with y1, direct global write ----
    if (w < 4) {
        const int r = (w << 4) + i;
        const float* y1r = s_y1 + (r >> 1) * SD + (dg << 5);
        float* yg = Yout + base + r * DD + (dg << 5);
#pragma unroll
        for (int cc = 0; cc < 8; cc++) {
            ulonglong2 u = *(const ulonglong2*)(y1r + cc * 4);
            u64 ox = add2(yp[2 * cc], u.x);
            u64 oy = add2(yp[2 * cc + 1], u.y);
            *(ulonglong2*)(yg + cc * 4) = make_ulonglong2(ox, oy);
        }
        if (dg == 0)
            Aout[(size_t)bh * (size_t)ntok + (size_t)c * 64 + r] = rs + s_a1[r >> 1];
    }
}

// ===========================================================================
// Level-8 micro kernel: 32 tokens/bh, 2 sibling-flipped blocks, 2 warps.
// ===========================================================================
__global__ void __launch_bounds__(64)
hatt_lvl8(const float* __restrict__ Q, const float* __restrict__ K,
          const float* __restrict__ V, float* __restrict__ Y,
          float* __restrict__ A)
{
    __shared__ float s_q[32 * SD], s_k[32 * SD], s_v[32 * SD];
    const int tid = threadIdx.x;
    const int bh = blockIdx.x;
    const size_t base = (size_t)bh * 32 * DD;
    const float4* qf = (const float4*)(Q + base);
    const float4* kf = (const float4*)(K + base);
    const float4* vf = (const float4*)(V + base);
    for (int idx = tid; idx < 512; idx += 64) {
        int row = idx >> 4, c4 = (idx & 15) << 2;
        *(float4*)(s_q + row * SD + c4) = qf[idx];
        *(float4*)(s_k + row * SD + c4) = kf[idx];
        *(float4*)(s_v + row * SD + c4) = vf[idx];
    }
    __syncthreads();

    const int w = tid >> 5, lane = tid & 31, i = lane & 15, dg = lane >> 4;
    const float* qB = s_q + w * 16 * SD;
    const float* kB = s_k + (w ^ 1) * 16 * SD;
    const float* vB = s_v + (w ^ 1) * 16 * SD;

    const float* qr = qB + i * SD;
    const float* kr = kB + dg * 8 * SD;
    u64 acc[8];
#pragma unroll
    for (int jj = 0; jj < 8; jj++) acc[jj] = 0ull;
#pragma unroll
    for (int c4 = 0; c4 < 16; c4++) {
        ulonglong2 qv = *(const ulonglong2*)(qr + c4 * 4);
#pragma unroll
        for (int jj = 0; jj < 8; jj++) {
            ulonglong2 kv = *(const ulonglong2*)(kr + jj * SD + c4 * 4);
            acc[jj] = fma2(qv.x, kv.x, acc[jj]);
            acc[jj] = fma2(qv.y, kv.y, acc[jj]);
        }
    }
    float s[8];
#pragma unroll
    for (int jj = 0; jj < 8; jj++) { float lo, hi; up2(acc[jj], lo, hi); s[jj] = lo + hi; }
    float m = s[0];
#pragma unroll
    for (int jj = 1; jj < 8; jj++) m = fmaxf(m, s[jj]);
    m = fmaxf(m, __shfl_xor_sync(0xffffffffu, m, 16));
    float Av[8];
    float rs = 0.f;
#pragma unroll
    for (int jj = 0; jj < 8; jj++) { Av[jj] = __expf(s[jj] - m); rs += Av[jj]; }
    rs += __shfl_xor_sync(0xffffffffu, rs, 16);
    float Af0[8], Af1[8];
#pragma unroll
    for (int jj = 0; jj < 8; jj++) {
        float o = __shfl_xor_sync(0xffffffffu, Av[jj], 16);
        Af0[jj] = dg ? o : Av[jj];
        Af1[jj] = dg ? Av[jj] : o;
    }

    u64 yp[16];
#pragma unroll
    for (int cc = 0; cc < 16; cc++) yp[cc] = 0ull;
#pragma unroll
    for (int jj = 0; jj < 8; jj++) {
        u64 a0 = pk2(Af0[jj], Af0[jj]);
        u64 a1 = pk2(Af1[jj], Af1[jj]);
        const ulonglong2* vr0 = (const ulonglong2*)(vB + jj * SD + (dg << 5));
        const ulonglong2* vr1 = (const ulonglong2*)(vB + (8 + jj) * SD + (dg << 5));
#pragma unroll
        for (int cc = 0; cc < 8; cc++) {
            ulonglong2 v0 = vr0[cc];
            ulonglong2 v1 = vr1[cc];
            yp[2 * cc]     = fma2(a0, v0.x, yp[2 * cc]);
            yp[2 * cc + 1] = fma2(a0, v0.y, yp[2 * cc + 1]);
            yp[2 * cc]     = fma2(a1, v1.x, yp[2 * cc]);
            yp[2 * cc + 1] = fma2(a1, v1.y, yp[2 * cc + 1]);
        }
    }
    float* yg = Y + base + ((w << 4) + i) * DD + (dg << 5);
#pragma unroll
    for (int cc = 0; cc < 8; cc++)
        *(ulonglong2*)(yg + cc * 4) = make_ulonglong2(yp[2 * cc], yp[2 * cc + 1]);
    if (dg == 0) A[bh * 32 + (w << 4) + i] = rs;
}

// ---------------------------------------------------------------------------
// Final combine:
// out[i] = (Y01[i]+Y23[i>>2]+Y45[i>>4]+Y67[i>>6]+Y8[i>>8]) / (sumA + eps)
// ---------------------------------------------------------------------------
__global__ __launch_bounds__(256)
void hatt_combine(float* __restrict__ out)
{
    unsigned idx = blockIdx.x * 256u + threadIdx.x;  // < 4194304 float4s
    unsigned f = idx & 15u;
    unsigned tok = (idx >> 4) & 8191u;
    unsigned bh = idx >> 17;

    float4 y = ((const float4*)g_Y01)[idx];
    float4 y2 = ((const float4*)g_Y23)[(((size_t)bh << 11) + (tok >> 2)) * 16 + f];
    float4 y4 = ((const float4*)g_Y45)[(((size_t)bh << 9) + (tok >> 4)) * 16 + f];
    float4 y6 = ((const float4*)g_Y67)[(((size_t)bh << 7) + (tok >> 6)) * 16 + f];
    float4 y8 = ((const float4*)g_Y8)[(((size_t)bh << 5) + (tok >> 8)) * 16 + f];
    float a = g_A01[((size_t)bh << 13) + tok]
            + g_A23[((size_t)bh << 11) + (tok >> 2)]
            + g_A45[((size_t)bh << 9) + (tok >> 4)]
            + g_A67[((size_t)bh << 7) + (tok >> 6)]
            + g_A8[((size_t)bh << 5) + (tok >> 8)] + 1e-8f;
    float inv = 1.0f / a;
    float4 o;
    o.x = (y.x + y2.x + y4.x + y6.x + y8.x) * inv;
    o.y = (y.y + y2.y + y4.y + y6.y + y8.y) * inv;
    o.z = (y.z + y2.z + y4.z + y6.z + y8.z) * inv;
    o.w = (y.w + y2.w + y4.w + y6.w + y8.w) * inv;
    ((float4*)out)[idx] = o;
}

// ---------------------------------------------------------------------------
extern "C" void kernel_launch(void* const* d_in, const int* in_sizes, int n_in,
                              void* d_out, int out_size)
{
    const float* q = (const float*)d_in[0];
    const float* k = (const float*)d_in[1];
    const float* v = (const float*)d_in[2];
    float* out = (float*)d_out;
    (void)in_sizes; (void)n_in; (void)out_size;

    void *Y01, *A01, *q2, *k2, *v2, *Y23, *A23, *q4, *k4, *v4, *Y45, *A45;
    void *q6, *k6, *v6, *Y67, *A67, *q8, *k8, *v8, *Y8, *A8;
    cudaGetSymbolAddress(&Y01, g_Y01);
    cudaGetSymbolAddress(&A01, g_A01);
    cudaGetSymbolAddress(&q2, g_q2);
    cudaGetSymbolAddress(&k2, g_k2);
    cudaGetSymbolAddress(&v2, g_v2);
    cudaGetSymbolAddress(&Y23, g_Y23);
    cudaGetSymbolAddress(&A23, g_A23);
    cudaGetSymbolAddress(&q4, g_q4);
    cudaGetSymbolAddress(&k4, g_k4);
    cudaGetSymbolAddress(&v4, g_v4);
    cudaGetSymbolAddress(&Y45, g_Y45);
    cudaGetSymbolAddress(&A45, g_A45);
    cudaGetSymbolAddress(&q6, g_q6);
    cudaGetSymbolAddress(&k6, g_k6);
    cudaGetSymbolAddress(&v6, g_v6);
    cudaGetSymbolAddress(&Y67, g_Y67);
    cudaGetSymbolAddress(&A67, g_A67);
    cudaGetSymbolAddress(&q8, g_q8);
    cudaGetSymbolAddress(&k8, g_k8);
    cudaGetSymbolAddress(&v8, g_v8);
    cudaGetSymbolAddress(&Y8, g_Y8);
    cudaGetSymbolAddress(&A8, g_A8);

    // bi: 64*SD*3 + 32*SD*3 + 32 = 19616 floats = 78464 B (2 CTAs/SM)
    const int smem_bi = (64 * SD * 3 + 32 * SD * 3 + 32) * (int)sizeof(float);
    cudaFuncSetAttribute(hatt_bi<false>, cudaFuncAttributeMaxDynamicSharedMemorySize, smem_bi);
    cudaFuncSetAttribute(hatt_bi<true>, cudaFuncAttributeMaxDynamicSharedMemorySize, smem_bi);

    // G0: levels 0-1 on original tokens (level 0 = self-attention, no flip).
    hatt_bi<false><<<dim3(128, 32), 256, smem_bi>>>(
        q, k, v, N0, 0.125f,
        (float*)Y01, (float*)A01, (float*)q2, (float*)k2, (float*)v2);

    // G1: levels 2-3 on pooled lvl2.
    hatt_bi<true><<<dim3(32, 32), 256, smem_bi>>>(
        (const float*)q2, (const float*)k2, (const float*)v2, N0 / 4, 1.0f,
        (float*)Y23, (float*)A23, (float*)q4, (float*)k4, (float*)v4);

    // G2: levels 4-5 on pooled lvl4.
    hatt_bi<true><<<dim3(8, 32), 256, smem_bi>>>(
        (const float*)q4, (const float*)k4, (const float*)v4, N0 / 16, 1.0f,
        (float*)Y45, (float*)A45, (float*)q6, (float*)k6, (float*)v6);

    // G3: levels 6-7 on pooled lvl6 (+pool lvl8).
    hatt_bi<true><<<dim3(2, 32), 256, smem_bi>>>(
        (const float*)q6, (const float*)k6, (const float*)v6, N0 / 64, 1.0f,
        (float*)Y67, (float*)A67, (float*)q8, (float*)k8, (float*)v8);

    // G4: level 8 micro kernel.
    hatt_lvl8<<<32, 64>>>(
        (const float*)q8, (const float*)k8, (const float*)v8,
        (float*)Y8, (float*)A8);

    // G5: final combine + divide.
    hatt_combine<<<4194304 / 256, 256>>>(out);
}

// round 10
// speedup vs baseline: 1.7015x; 1.0238x over previous
#include <cuda_runtime.h>

// ---------------------------------------------------------------------------
// HAttention1D: b=4 h=8 n=8192 d=64, block=16, 9 levels (0..8).
// R9: inverted pass order to eliminate the Y01 materialization.
//   K_A  hatt_lvl23  : orig->pool x4 in regs, attn lvl2-3, emit pooled
//                      lvl4+lvl6+lvl8 (warps 6/7).
//   K_T  hatt_tail   : ONE kernel, 352 CTAs: lvl4-5 (256), lvl6-7 (64),
//                      lvl8 (32).
//   K_F  hatt_fused01: attn lvl0-1 + staged coarse Y/A + divide -> out.
// ---------------------------------------------------------------------------

#define BHN 32
#define N0  8192
#define DD  64
#define SD  68   // padded smem row stride in floats

typedef unsigned long long u64;

// ---- packed f32x2 helpers ----
__device__ __forceinline__ u64 pk2(float a, float b) {
    u64 r; asm("mov.b64 %0, {%1, %2};" : "=l"(r) : "f"(a), "f"(b)); return r;
}
__device__ __forceinline__ void up2(u64 v, float& a, float& b) {
    asm("mov.b64 {%0, %1}, %2;" : "=f"(a), "=f"(b) : "l"(v));
}
__device__ __forceinline__ u64 fma2(u64 a, u64 b, u64 c) {
    u64 r; asm("fma.rn.f32x2 %0, %1, %2, %3;" : "=l"(r) : "l"(a), "l"(b), "l"(c)); return r;
}
__device__ __forceinline__ u64 add2(u64 a, u64 b) {
    u64 r; asm("add.rn.f32x2 %0, %1, %2;" : "=l"(r) : "l"(a), "l"(b)); return r;
}
__device__ __forceinline__ u64 mul2(u64 a, u64 b) {
    u64 r; asm("mul.rn.f32x2 %0, %1, %2;" : "=l"(r) : "l"(a), "l"(b)); return r;
}

// ---- scratch (device globals; no allocations allowed) ----
__device__ __align__(16) float g_Y23[(size_t)BHN * (N0 / 4) * DD];   // 16 MB
__device__ __align__(16) float g_A23[BHN * (N0 / 4)];
__device__ __align__(16) float g_q4[BHN * (N0 / 16) * DD];           // 4 MB ea
__device__ __align__(16) float g_k4[BHN * (N0 / 16) * DD];
__device__ __align__(16) float g_v4[BHN * (N0 / 16) * DD];
__device__ __align__(16) float g_Y45[BHN * (N0 / 16) * DD];
__device__ __align__(16) float g_A45[BHN * (N0 / 16)];
__device__ __align__(16) float g_q6[BHN * (N0 / 64) * DD];           // 1 MB ea
__device__ __align__(16) float g_k6[BHN * (N0 / 64) * DD];
__device__ __align__(16) float g_v6[BHN * (N0 / 64) * DD];
__device__ __align__(16) float g_Y67[BHN * (N0 / 64) * DD];
__device__ __align__(16) float g_A67[BHN * (N0 / 64)];
__device__ __align__(16) float g_q8[BHN * (N0 / 256) * DD];          // 256 KB ea
__device__ __align__(16) float g_k8[BHN * (N0 / 256) * DD];
__device__ __align__(16) float g_v8[BHN * (N0 / 256) * DD];
__device__ __align__(16) float g_Y8[BHN * (N0 / 256) * DD];
__device__ __align__(16) float g_A8[BHN * (N0 / 256)];

__device__ __forceinline__ float4 f4_scale(float4 a, float s) {
    return make_float4(a.x * s, a.y * s, a.z * s, a.w * s);
}
__device__ __forceinline__ float4 f4_add(float4 a, float4 b) {
    return make_float4(a.x + b.x, a.y + b.y, a.z + b.z, a.w + b.w);
}
__device__ __forceinline__ float4 f4_avg(float4 a, float4 b) {
    return make_float4((a.x + b.x) * 0.5f, (a.y + b.y) * 0.5f,
                       (a.z + b.z) * 0.5f, (a.w + b.w) * 0.5f);
}

// ---------------------------------------------------------------------------
// One warp: full 16x16 block attention. Lane (i, dg): query row i, d-half dg.
// Returns row sum rs; fills yp with 16 packed f32x2 accumulators covering
// dims [dg*32, dg*32+32) of row i. No syncs inside (warp-local + shfl only).
// ---------------------------------------------------------------------------
__device__ __forceinline__ float attn_block(
    const float* __restrict__ qB, const float* __restrict__ kB,
    const float* __restrict__ vB, int i, int dg, u64 yp[16])
{
    const float* qr = qB + i * SD;
    const float* kr = kB + dg * 8 * SD;
    u64 acc[8];
#pragma unroll
    for (int jj = 0; jj < 8; jj++) acc[jj] = 0ull;
#pragma unroll
    for (int c4 = 0; c4 < 16; c4++) {
        ulonglong2 qv = *(const ulonglong2*)(qr + c4 * 4);
#pragma unroll
        for (int jj = 0; jj < 8; jj++) {
            ulonglong2 kv = *(const ulonglong2*)(kr + jj * SD + c4 * 4);
            acc[jj] = fma2(qv.x, kv.x, acc[jj]);
            acc[jj] = fma2(qv.y, kv.y, acc[jj]);
        }
    }
    float s[8];
#pragma unroll
    for (int jj = 0; jj < 8; jj++) { float lo, hi; up2(acc[jj], lo, hi); s[jj] = lo + hi; }
    float m = s[0];
#pragma unroll
    for (int jj = 1; jj < 8; jj++) m = fmaxf(m, s[jj]);
    m = fmaxf(m, __shfl_xor_sync(0xffffffffu, m, 16));
    float A[8];
    float rs = 0.f;
#pragma unroll
    for (int jj = 0; jj < 8; jj++) { A[jj] = __expf(s[jj] - m); rs += A[jj]; }
    rs += __shfl_xor_sync(0xffffffffu, rs, 16);
    float Af0[8], Af1[8];
#pragma unroll
    for (int jj = 0; jj < 8; jj++) {
        float o = __shfl_xor_sync(0xffffffffu, A[jj], 16);
        Af0[jj] = dg ? o : A[jj];
        Af1[jj] = dg ? A[jj] : o;
    }
#pragma unroll
    for (int cc = 0; cc < 16; cc++) yp[cc] = 0ull;
#pragma unroll
    for (int jj = 0; jj < 8; jj++) {
        u64 a0 = pk2(Af0[jj], Af0[jj]);
        u64 a1 = pk2(Af1[jj], Af1[jj]);
        const ulonglong2* vr0 = (const ulonglong2*)(vB + jj * SD + (dg << 5));
        const ulonglong2* vr1 = (const ulonglong2*)(vB + (8 + jj) * SD + (dg << 5));
#pragma unroll
        for (int cc = 0; cc < 8; cc++) {
            ulonglong2 v0 = vr0[cc];
            ulonglong2 v1 = vr1[cc];
            yp[2 * cc]     = fma2(a0, v0.x, yp[2 * cc]);
            yp[2 * cc + 1] = fma2(a0, v0.y, yp[2 * cc + 1]);
            yp[2 * cc]     = fma2(a1, v1.x, yp[2 * cc]);
            yp[2 * cc + 1] = fma2(a1, v1.y, yp[2 * cc + 1]);
        }
    }
    return rs;
}

// ===========================================================================
// K_A: levels 2-3 from ORIGINAL inputs (pool x4 in registers during load).
// Chunk = 256 orig tokens = 64 lvl2 tokens. Warps 0-3: lvl2 blocks (flip);
// 4-5: lvl3 blocks (flip); 6: lvl6 pool-out; 7: lvl8 pool-out.
// Also writes pooled lvl4 (from Phase 1) to global.
// ===========================================================================
__global__ void __launch_bounds__(256, 2)
hatt_lvl23(const float* __restrict__ Q, const float* __restrict__ K,
           const float* __restrict__ V,
           float* __restrict__ Y23, float* __restrict__ A23,
           float* __restrict__ q4, float* __restrict__ k4, float* __restrict__ v4,
           float* __restrict__ q6, float* __restrict__ k6, float* __restrict__ v6,
           float* __restrict__ q8, float* __restrict__ k8, float* __restrict__ v8)
{
    extern __shared__ float sm[];
    float* s_q0 = sm;                     // 64*SD  (lvl2)
    float* s_k0 = s_q0 + 64 * SD;
    float* s_v0 = s_k0 + 64 * SD;
    float* s_q1 = s_v0 + 64 * SD;         // 32*SD  (lvl3)
    float* s_k1 = s_q1 + 32 * SD;
    float* s_v1 = s_k1 + 32 * SD;
    float* s_y1 = s_v1 + 32 * SD;         // 32*SD
    float* s_a1 = s_y1 + 32 * SD;         // 32
    float* s_p4q = s_a1 + 32;             // 16*SD (lvl4 stage)
    float* s_p4k = s_p4q + 16 * SD;
    float* s_p4v = s_p4k + 16 * SD;

    const int tid = threadIdx.x;
    const int bh = blockIdx.y;
    const int c = blockIdx.x;             // 0..31
    const size_t baseO = ((size_t)bh * N0 + (size_t)c * 256) * DD;

    // ---- Phase 1: each thread loads 16 orig rows at one f4-col, pools ----
    {
        const int u = tid >> 4, cq = tid & 15, c4 = cq << 2;
        const float4* qf = (const float4*)(Q + baseO);
        const float4* kf = (const float4*)(K + baseO);
        const float4* vf = (const float4*)(V + baseO);
        const int i0 = (u << 8) + cq;
        float4 l2q[4], l2k[4], l2v[4];
#pragma unroll
        for (int g = 0; g < 4; g++) {
            int ib = i0 + (g << 6);
            float4 a0 = qf[ib], a1 = qf[ib + 16], a2 = qf[ib + 32], a3 = qf[ib + 48];
            l2q[g] = f4_scale(f4_avg(f4_avg(a0, a1), f4_avg(a2, a3)), 0.125f);
            float4 b0 = kf[ib], b1 = kf[ib + 16], b2 = kf[ib + 32], b3 = kf[ib + 48];
            l2k[g] = f4_avg(f4_avg(b0, b1), f4_avg(b2, b3));
            float4 d0 = vf[ib], d1 = vf[ib + 16], d2 = vf[ib + 32], d3 = vf[ib + 48];
            l2v[g] = f4_add(f4_add(d0, d1), f4_add(d2, d3));
        }
        const int r0 = (u << 2) * SD + c4;
#pragma unroll
        for (int g = 0; g < 4; g++) {
            *(float4*)(s_q0 + r0 + g * SD) = l2q[g];
            *(float4*)(s_k0 + r0 + g * SD) = l2k[g];
            *(float4*)(s_v0 + r0 + g * SD) = l2v[g];
        }
        float4 q3a = f4_avg(l2q[0], l2q[1]), q3b = f4_avg(l2q[2], l2q[3]);
        float4 k3a = f4_avg(l2k[0], l2k[1]), k3b = f4_avg(l2k[2], l2k[3]);
        float4 v3a = f4_add(l2v[0], l2v[1]), v3b = f4_add(l2v[2], l2v[3]);
        const int r1 = (u << 1) * SD + c4;
        *(float4*)(s_q1 + r1) = q3a;  *(float4*)(s_q1 + r1 + SD) = q3b;
        *(float4*)(s_k1 + r1) = k3a;  *(float4*)(s_k1 + r1 + SD) = k3b;
        *(float4*)(s_v1 + r1) = v3a;  *(float4*)(s_v1 + r1 + SD) = v3b;
        float4 q4r = f4_avg(q3a, q3b), k4r = f4_avg(k3a, k3b), v4r = f4_add(v3a, v3b);
        *(float4*)(s_p4q + u * SD + c4) = q4r;
        *(float4*)(s_p4k + u * SD + c4) = k4r;
        *(float4*)(s_p4v + u * SD + c4) = v4r;
        const size_t gi = ((size_t)(bh * 512 + c * 16 + u)) * 16 + cq;
        ((float4*)q4)[gi] = q4r; ((float4*)k4)[gi] = k4r; ((float4*)v4)[gi] = v4r;
    }
    __syncthreads();

    const int w = tid >> 5, lane = tid & 31, i = lane & 15, dg = lane >> 4;
    u64 yp[16];
    float rs = 0.f;
    if (w < 4) {
        int sb = w ^ 1;
        rs = attn_block(s_q0 + w * 16 * SD, s_k0 + sb * 16 * SD,
                        s_v0 + sb * 16 * SD, i, dg, yp);
    } else if (w < 6) {
        int qb = w - 4, sb = qb ^ 1;
        rs = attn_block(s_q1 + qb * 16 * SD, s_k1 + sb * 16 * SD,
                        s_v1 + sb * 16 * SD, i, dg, yp);
        float* yo = s_y1 + (qb * 16 + i) * SD + (dg << 5);
#pragma unroll
        for (int cc = 0; cc < 8; cc++)
            *(ulonglong2*)(yo + cc * 4) = make_ulonglong2(yp[2 * cc], yp[2 * cc + 1]);
        if (dg == 0) s_a1[qb * 16 + i] = rs;
    } else if (w == 6) {
        // lvl6 pool-out: 4 rows x 16 cols from the 16 staged lvl4 rows
#pragma unroll
        for (int it = 0; it < 2; it++) {
            int idx = (it << 5) + lane;
            int t = idx >> 4, cq = idx & 15, c4s = cq << 2;
            const float* pq = s_p4q + (t << 2) * SD + c4s;
            const float* pk = s_p4k + (t << 2) * SD + c4s;
            const float* pv = s_p4v + (t << 2) * SD + c4s;
            float4 r6q = f4_avg(f4_avg(*(const float4*)pq, *(const float4*)(pq + SD)),
                                f4_avg(*(const float4*)(pq + 2 * SD), *(const float4*)(pq + 3 * SD)));
            float4 r6k = f4_avg(f4_avg(*(const float4*)pk, *(const float4*)(pk + SD)),
                                f4_avg(*(const float4*)(pk + 2 * SD), *(const float4*)(pk + 3 * SD)));
            float4 r6v = f4_add(f4_add(*(const float4*)pv, *(const float4*)(pv + SD)),
                                f4_add(*(const float4*)(pv + 2 * SD), *(const float4*)(pv + 3 * SD)));
            const size_t gi = ((size_t)(bh * 128 + (c << 2) + t)) * 16 + cq;
            ((float4*)q6)[gi] = r6q; ((float4*)k6)[gi] = r6k; ((float4*)v6)[gi] = r6v;
        }
    } else {
        // lvl8 pool-out: 1 row per chunk; pairwise tree over 16 lvl4 rows.
        if (lane < 16) {
            int c4s = lane << 2;
            const size_t gi = ((size_t)(bh * 32 + c)) * 16 + lane;
            {   // q (avg tree)
                float4 t5[8];
#pragma unroll
                for (int j = 0; j < 8; j++) {
                    const float* p = s_p4q + (2 * j) * SD + c4s;
                    t5[j] = f4_avg(*(const float4*)p, *(const float4*)(p + SD));
                }
                float4 t6a = f4_avg(t5[0], t5[1]), t6b = f4_avg(t5[2], t5[3]);
                float4 t6c = f4_avg(t5[4], t5[5]), t6d = f4_avg(t5[6], t5[7]);
                ((float4*)q8)[gi] = f4_avg(f4_avg(t6a, t6b), f4_avg(t6c, t6d));
            }
            {   // k (avg tree)
                float4 t5[8];
#pragma unroll
                for (int j = 0; j < 8; j++) {
                    const float* p = s_p4k + (2 * j) * SD + c4s;
                    t5[j] = f4_avg(*(const float4*)p, *(const float4*)(p + SD));
                }
                float4 t6a = f4_avg(t5[0], t5[1]), t6b = f4_avg(t5[2], t5[3]);
                float4 t6c = f4_avg(t5[4], t5[5]), t6d = f4_avg(t5[6], t5[7]);
                ((float4*)k8)[gi] = f4_avg(f4_avg(t6a, t6b), f4_avg(t6c, t6d));
            }
            {   // v (sum tree)
                float4 t5[8];
#pragma unroll
                for (int j = 0; j < 8; j++) {
                    const float* p = s_p4v + (2 * j) * SD + c4s;
                    t5[j] = f4_add(*(const float4*)p, *(const float4*)(p + SD));
                }
                float4 t6a = f4_add(t5[0], t5[1]), t6b = f4_add(t5[2], t5[3]);
                float4 t6c = f4_add(t5[4], t5[5]), t6d = f4_add(t5[6], t5[7]);
                ((float4*)v8)[gi] = f4_add(f4_add(t6a, t6b), f4_add(t6c, t6d));
            }
        }
    }
    __syncthreads();

    if (w < 4) {
        const int r = (w << 4) + i;
        const float* y1r = s_y1 + (r >> 1) * SD + (dg << 5);
        float* yg = Y23 + ((size_t)bh * 2048 + (size_t)c * 64 + r) * DD + (dg << 5);
#pragma unroll
        for (int cc = 0; cc < 8; cc++) {
            ulonglong2 u1 = *(const ulonglong2*)(y1r + cc * 4);
            *(ulonglong2*)(yg + cc * 4) =
                make_ulonglong2(add2(yp[2 * cc], u1.x), add2(yp[2 * cc + 1], u1.y));
        }
        if (dg == 0)
            A23[bh * 2048 + c * 64 + r] = rs + s_a1[r >> 1];
    }
}

// ===========================================================================
// K_T: fused tail. 352 CTAs: [0,256) lvl4-5; [256,320) lvl6-7; [320,352) lvl8.
// ===========================================================================
__global__ void __launch_bounds__(256, 2)
hatt_tail(const float* __restrict__ q4, const float* __restrict__ k4,
          const float* __restrict__ v4, float* __restrict__ Y45, float* __restrict__ A45,
          const float* __restrict__ q6, const float* __restrict__ k6,
          const float* __restrict__ v6, float* __restrict__ Y67, float* __restrict__ A67,
          const float* __restrict__ q8, const float* __restrict__ k8,
          const float* __restrict__ v8, float* __restrict__ Y8, float* __restrict__ A8)
{
    extern __shared__ float sm[];
    float* s_q0 = sm;                     // 64*SD
    float* s_k0 = s_q0 + 64 * SD;
    float* s_v0 = s_k0 + 64 * SD;
    float* s_q1 = s_v0 + 64 * SD;         // 32*SD
    float* s_k1 = s_q1 + 32 * SD;
    float* s_v1 = s_k1 + 32 * SD;
    float* s_y1 = s_v1 + 32 * SD;         // 32*SD
    float* s_a1 = s_y1 + 32 * SD;         // 32

    const int tid = threadIdx.x;
    const int bid = blockIdx.x;
    const int w = tid >> 5, lane = tid & 31, i = lane & 15, dg = lane >> 4;

    if (bid < 320) {
        const float *Q, *K, *V;
        float *Yd, *Ad;
        int ntok, c, bh;
        if (bid < 256) {
            bh = bid >> 3; c = bid & 7; ntok = 512;
            Q = q4; K = k4; V = v4; Yd = Y45; Ad = A45;
        } else {
            int b2 = bid - 256;
            bh = b2 >> 1; c = b2 & 1; ntok = 128;
            Q = q6; K = k6; V = v6; Yd = Y67; Ad = A67;
        }
        const size_t base = ((size_t)bh * ntok + (size_t)c * 64) * DD;

        // Phase 1: 4 consecutive rows/thread + thread-local pooling
        {
            const int u = tid >> 4, cq = tid & 15, c4 = cq << 2;
            const float4* qf = (const float4*)(Q + base);
            const float4* kf = (const float4*)(K + base);
            const float4* vf = (const float4*)(V + base);
            const int i0 = (u << 6) + cq;
            float4 a0 = qf[i0], a1 = qf[i0 + 16], a2 = qf[i0 + 32], a3 = qf[i0 + 48];
            float4 b0 = kf[i0], b1 = kf[i0 + 16], b2 = kf[i0 + 32], b3 = kf[i0 + 48];
            float4 d0 = vf[i0], d1 = vf[i0 + 16], d2 = vf[i0 + 32], d3 = vf[i0 + 48];
            const int r0 = (u << 2) * SD + c4;
            *(float4*)(s_q0 + r0) = a0;           *(float4*)(s_q0 + r0 + SD) = a1;
            *(float4*)(s_q0 + r0 + 2 * SD) = a2;  *(float4*)(s_q0 + r0 + 3 * SD) = a3;
            *(float4*)(s_k0 + r0) = b0;           *(float4*)(s_k0 + r0 + SD) = b1;
            *(float4*)(s_k0 + r0 + 2 * SD) = b2;  *(float4*)(s_k0 + r0 + 3 * SD) = b3;
            *(float4*)(s_v0 + r0) = d0;           *(float4*)(s_v0 + r0 + SD) = d1;
            *(float4*)(s_v0 + r0 + 2 * SD) = d2;  *(float4*)(s_v0 + r0 + 3 * SD) = d3;
            const int r1 = (u << 1) * SD + c4;
            *(float4*)(s_q1 + r1) = f4_avg(a0, a1);  *(float4*)(s_q1 + r1 + SD) = f4_avg(a2, a3);
            *(float4*)(s_k1 + r1) = f4_avg(b0, b1);  *(float4*)(s_k1 + r1 + SD) = f4_avg(b2, b3);
            *(float4*)(s_v1 + r1) = f4_add(d0, d1);  *(float4*)(s_v1 + r1 + SD) = f4_add(d2, d3);
        }
        __syncthreads();

        u64 yp[16];
        float rs = 0.f;
        if (w < 4) {
            int sb = w ^ 1;
            rs = attn_block(s_q0 + w * 16 * SD, s_k0 + sb * 16 * SD,
                            s_v0 + sb * 16 * SD, i, dg, yp);
        } else if (w < 6) {
            int qb = w - 4, sb = qb ^ 1;
            rs = attn_block(s_q1 + qb * 16 * SD, s_k1 + sb * 16 * SD,
                            s_v1 + sb * 16 * SD, i, dg, yp);
            float* yo = s_y1 + (qb * 16 + i) * SD + (dg << 5);
#pragma unroll
            for (int cc = 0; cc < 8; cc++)
                *(ulonglong2*)(yo + cc * 4) = make_ulonglong2(yp[2 * cc], yp[2 * cc + 1]);
            if (dg == 0) s_a1[qb * 16 + i] = rs;
        }
        __syncthreads();

        if (w < 4) {
            const int r = (w << 4) + i;
            const float* y1r = s_y1 + (r >> 1) * SD + (dg << 5);
            float* yg = Yd + base + (size_t)r * DD + (dg << 5);
#pragma unroll
            for (int cc = 0; cc < 8; cc++) {
                ulonglong2 u1 = *(const ulonglong2*)(y1r + cc * 4);
                *(ulonglong2*)(yg + cc * 4) =
                    make_ulonglong2(add2(yp[2 * cc], u1.x), add2(yp[2 * cc + 1], u1.y));
            }
            if (dg == 0)
                Ad[bh * ntok + c * 64 + r] = rs + s_a1[r >> 1];
        }
    } else {
        // ---- lvl8: 32 tokens, 2 sibling-flipped blocks ----
        const int bh = bid - 320;
        const size_t base = (size_t)bh * 32 * DD;
        const float4* qf = (const float4*)(q8 + base);
        const float4* kf = (const float4*)(k8 + base);
        const float4* vf = (const float4*)(v8 + base);
        for (int idx = tid; idx < 512; idx += 256) {
            int row = idx >> 4, c4 = (idx & 15) << 2;
            *(float4*)(s_q0 + row * SD + c4) = qf[idx];
            *(float4*)(s_k0 + row * SD + c4) = kf[idx];
            *(float4*)(s_v0 + row * SD + c4) = vf[idx];
        }
        __syncthreads();
        if (w < 2) {
            u64 yp[16];
            float rs = attn_block(s_q0 + w * 16 * SD, s_k0 + (w ^ 1) * 16 * SD,
                                  s_v0 + (w ^ 1) * 16 * SD, i, dg, yp);
            float* yg = Y8 + base + (size_t)((w << 4) + i) * DD + (dg << 5);
#pragma unroll
            for (int cc = 0; cc < 8; cc++)
                *(ulonglong2*)(yg + cc * 4) = make_ulonglong2(yp[2 * cc], yp[2 * cc + 1]);
            if (dg == 0) A8[bh * 32 + (w << 4) + i] = rs;
        }
    }
}

// ===========================================================================
// K_F: levels 0-1 + final combine. Warps 6/7 stage coarse Y/A into smem
// during the attention phase; Phase C sums all levels, divides, writes out.
// ===========================================================================
__global__ void __launch_bounds__(256, 2)
hatt_fused01(const float* __restrict__ Q, const float* __restrict__ K,
             const float* __restrict__ V, float* __restrict__ out,
             const float* __restrict__ Y23, const float* __restrict__ A23,
             const float* __restrict__ Y45, const float* __restrict__ A45,
             const float* __restrict__ Y67, const float* __restrict__ A67,
             const float* __restrict__ Y8, const float* __restrict__ A8)
{
    extern __shared__ float sm[];
    float* s_q0 = sm;                     // 64*SD
    float* s_k0 = s_q0 + 64 * SD;
    float* s_v0 = s_k0 + 64 * SD;
    float* s_q1 = s_v0 + 64 * SD;         // 32*SD
    float* s_k1 = s_q1 + 32 * SD;
    float* s_v1 = s_k1 + 32 * SD;
    float* s_y1 = s_v1 + 32 * SD;         // 32*SD
    float* s_a1 = s_y1 + 32 * SD;         // 32
    float* s_c = s_a1 + 32;               // 22*SD coarse Y stage
    float* s_ca = s_c + 22 * SD;          // 22 coarse A stage

    const int tid = threadIdx.x;
    const int bh = blockIdx.y;
    const int c = blockIdx.x;             // 0..127
    const size_t base = ((size_t)bh * N0 + (size_t)c * 64) * DD;

    // ---- Phase 1: load 64 orig rows (scaled q) + pool lvl1 locally ----
    {
        const int u = tid >> 4, cq = tid & 15, c4 = cq << 2;
        const float4* qf = (const float4*)(Q + base);
        const float4* kf = (const float4*)(K + base);
        const float4* vf = (const float4*)(V + base);
        const int i0 = (u << 6) + cq;
        float4 a0 = f4_scale(qf[i0], 0.125f), a1 = f4_scale(qf[i0 + 16], 0.125f);
        float4 a2 = f4_scale(qf[i0 + 32], 0.125f), a3 = f4_scale(qf[i0 + 48], 0.125f);
        float4 b0 = kf[i0], b1 = kf[i0 + 16], b2 = kf[i0 + 32], b3 = kf[i0 + 48];
        float4 d0 = vf[i0], d1 = vf[i0 + 16], d2 = vf[i0 + 32], d3 = vf[i0 + 48];
        const int r0 = (u << 2) * SD + c4;
        *(float4*)(s_q0 + r0) = a0;           *(float4*)(s_q0 + r0 + SD) = a1;
        *(float4*)(s_q0 + r0 + 2 * SD) = a2;  *(float4*)(s_q0 + r0 + 3 * SD) = a3;
        *(float4*)(s_k0 + r0) = b0;           *(float4*)(s_k0 + r0 + SD) = b1;
        *(float4*)(s_k0 + r0 + 2 * SD) = b2;  *(float4*)(s_k0 + r0 + 3 * SD) = b3;
        *(float4*)(s_v0 + r0) = d0;           *(float4*)(s_v0 + r0 + SD) = d1;
        *(float4*)(s_v0 + r0 + 2 * SD) = d2;  *(float4*)(s_v0 + r0 + 3 * SD) = d3;
        const int r1 = (u << 1) * SD + c4;
        *(float4*)(s_q1 + r1) = f4_avg(a0, a1);  *(float4*)(s_q1 + r1 + SD) = f4_avg(a2, a3);
        *(float4*)(s_k1 + r1) = f4_avg(b0, b1);  *(float4*)(s_k1 + r1 + SD) = f4_avg(b2, b3);
        *(float4*)(s_v1 + r1) = f4_add(d0, d1);  *(float4*)(s_v1 + r1 + SD) = f4_add(d2, d3);
    }
    __syncthreads();

    const int w = tid >> 5, lane = tid & 31, i = lane & 15, dg = lane >> 4;
    u64 yp[16];
    float rs = 0.f;
    if (w < 4) {
        // level 0: SELF-attention (no flip)
        rs = attn_block(s_q0 + w * 16 * SD, s_k0 + w * 16 * SD,
                        s_v0 + w * 16 * SD, i, dg, yp);
    } else if (w < 6) {
        int qb = w - 4, sb = qb ^ 1;
        rs = attn_block(s_q1 + qb * 16 * SD, s_k1 + sb * 16 * SD,
                        s_v1 + sb * 16 * SD, i, dg, yp);
        float* yo = s_y1 + (qb * 16 + i) * SD + (dg << 5);
#pragma unroll
        for (int cc = 0; cc < 8; cc++)
            *(ulonglong2*)(yo + cc * 4) = make_ulonglong2(yp[2 * cc], yp[2 * cc + 1]);
        if (dg == 0) s_a1[qb * 16 + i] = rs;
    } else if (w == 6) {
        // stage Y23: 16 rows (rows 0-15 of s_c)
        const float4* y23f = (const float4*)Y23;
#pragma unroll
        for (int it = 0; it < 8; it++) {
            int idx = (it << 5) + lane;
            int t = idx >> 4, cq = idx & 15;
            *(float4*)(s_c + t * SD + (cq << 2)) =
                y23f[((size_t)bh * 2048 + (size_t)c * 16 + t) * 16 + cq];
        }
    } else {
        // w==7: stage Y45 (rows 16-19), Y67 (20), Y8 (21), all coarse A's
        const float4* y45f = (const float4*)Y45;
#pragma unroll
        for (int it = 0; it < 2; it++) {
            int idx = (it << 5) + lane;
            int t = idx >> 4, cq = idx & 15;
            *(float4*)(s_c + (16 + t) * SD + (cq << 2)) =
                y45f[((size_t)bh * 512 + (size_t)c * 4 + t) * 16 + cq];
        }
        if (lane < 16) {
            *(float4*)(s_c + 20 * SD + (lane << 2)) =
                ((const float4*)Y67)[((size_t)bh * 128 + c) * 16 + lane];
            *(float4*)(s_c + 21 * SD + (lane << 2)) =
                ((const float4*)Y8)[((size_t)bh * 32 + (c >> 2)) * 16 + lane];
            s_ca[lane] = A23[bh * 2048 + c * 16 + lane];
        }
        if (lane < 4) s_ca[16 + lane] = A45[bh * 512 + c * 4 + lane];
        if (lane == 0) {
            s_ca[20] = A67[bh * 128 + c];
            s_ca[21] = A8[bh * 32 + (c >> 2)];
        }
    }
    __syncthreads();

    // ---- Phase C (w 0-3): sum all levels, divide, write out ----
    if (w < 4) {
        const int r = (w << 4) + i;
        float a = rs + s_a1[r >> 1] + s_ca[r >> 2] + s_ca[16 + (r >> 4)]
                + s_ca[20] + s_ca[21] + 1e-8f;
        float inv = 1.0f / a;
        u64 inv2 = pk2(inv, inv);
        const float* y1r = s_y1 + (r >> 1) * SD + (dg << 5);
        const float* c2p = s_c + (r >> 2) * SD + (dg << 5);
        const float* c4p = s_c + (16 + (r >> 4)) * SD + (dg << 5);
        const float* c6p = s_c + 20 * SD + (dg << 5);
        const float* c8p = s_c + 21 * SD + (dg << 5);
        float* yg = out + base + (size_t)r * DD + (dg << 5);
#pragma unroll
        for (int cc = 0; cc < 8; cc++) {
            ulonglong2 u1 = *(const ulonglong2*)(y1r + cc * 4);
            ulonglong2 u2 = *(const ulonglong2*)(c2p + cc * 4);
            ulonglong2 u4 = *(const ulonglong2*)(c4p + cc * 4);
            ulonglong2 u6 = *(const ulonglong2*)(c6p + cc * 4);
            ulonglong2 u8 = *(const ulonglong2*)(c8p + cc * 4);
            u64 sx = add2(add2(yp[2 * cc], u1.x),
                          add2(add2(u2.x, u4.x), add2(u6.x, u8.x)));
            u64 sy = add2(add2(yp[2 * cc + 1], u1.y),
                          add2(add2(u2.y, u4.y), add2(u6.y, u8.y)));
            *(ulonglong2*)(yg + cc * 4) = make_ulonglong2(mul2(sx, inv2), mul2(sy, inv2));
        }
    }
}

// ---------------------------------------------------------------------------
extern "C" void kernel_launch(void* const* d_in, const int* in_sizes, int n_in,
                              void* d_out, int out_size)
{
    const float* q = (const float*)d_in[0];
    const float* k = (const float*)d_in[1];
    const float* v = (const float*)d_in[2];
    float* out = (float*)d_out;
    (void)in_sizes; (void)n_in; (void)out_size;

    void *Y23, *A23, *q4, *k4, *v4, *Y45, *A45, *q6, *k6, *v6, *Y67, *A67;
    void *q8, *k8, *v8, *Y8, *A8;
    cudaGetSymbolAddress(&Y23, g_Y23);
    cudaGetSymbolAddress(&A23, g_A23);
    cudaGetSymbolAddress(&q4, g_q4);
    cudaGetSymbolAddress(&k4, g_k4);
    cudaGetSymbolAddress(&v4, g_v4);
    cudaGetSymbolAddress(&Y45, g_Y45);
    cudaGetSymbolAddress(&A45, g_A45);
    cudaGetSymbolAddress(&q6, g_q6);
    cudaGetSymbolAddress(&k6, g_k6);
    cudaGetSymbolAddress(&v6, g_v6);
    cudaGetSymbolAddress(&Y67, g_Y67);
    cudaGetSymbolAddress(&A67, g_A67);
    cudaGetSymbolAddress(&q8, g_q8);
    cudaGetSymbolAddress(&k8, g_k8);
    cudaGetSymbolAddress(&v8, g_v8);
    cudaGetSymbolAddress(&Y8, g_Y8);
    cudaGetSymbolAddress(&A8, g_A8);

    // smem sizes (floats)
    const int S23 = (64 * SD * 3 + 32 * SD * 4 + 32 + 16 * SD * 3) * (int)sizeof(float); // 100224
    const int ST  = (64 * SD * 3 + 32 * SD * 4 + 32) * (int)sizeof(float);               // 87168
    const int SF  = (64 * SD * 3 + 32 * SD * 4 + 32 + 22 * SD + 22) * (int)sizeof(float);// 93240
    cudaFuncSetAttribute(hatt_lvl23, cudaFuncAttributeMaxDynamicSharedMemorySize, S23);
    cudaFuncSetAttribute(hatt_tail, cudaFuncAttributeMaxDynamicSharedMemorySize, ST);
    cudaFuncSetAttribute(hatt_fused01, cudaFuncAttributeMaxDynamicSharedMemorySize, SF);

    // K_A: levels 2-3 from original (pool x4 in regs) + pooled lvl4/6/8 out.
    hatt_lvl23<<<dim3(32, 32), 256, S23>>>(
        q, k, v, (float*)Y23, (float*)A23,
        (float*)q4, (float*)k4, (float*)v4,
        (float*)q6, (float*)k6, (float*)v6,
        (float*)q8, (float*)k8, (float*)v8);

    // K_T: fused tail (levels 4-5, 6-7, 8) in one launch.
    hatt_tail<<<352, 256, ST>>>(
        (const float*)q4, (const float*)k4, (const float*)v4, (float*)Y45, (float*)A45,
        (const float*)q6, (const float*)k6, (const float*)v6, (float*)Y67, (float*)A67,
        (const float*)q8, (const float*)k8, (const float*)v8, (float*)Y8, (float*)A8);

    // K_F: levels 0-1 + combine + divide -> out.
    hatt_fused01<<<dim3(128, 32), 256, SF>>>(
        q, k, v, out,
        (const float*)Y23, (const float*)A23, (const float*)Y45, (const float*)A45,
        (const float*)Y67, (const float*)A67, (const float*)Y8, (const float*)A8);
}